// round 8
// baseline (speedup 1.0000x reference)
#include <cuda_runtime.h>
#include <cuda_bf16.h>
#include <cstdint>

#define NN 100000
#define EE 1600000
#define FULL 0xffffffffu
#define NB_SCAN 196

// ---------------- scratch (static device globals; no allocation) ----------------
__device__ __align__(16) int   g_cnt[NN];
__device__ __align__(16) int   g_row_start[NN + 1];
__device__ __align__(16) int   g_cursor[NN];
__device__ __align__(16) int   g_csr[EE];
__device__ __align__(16) unsigned int g_state[256];       // lookback: flag(2b)|value(30b)
__device__ __align__(16) float g_aggx[12800000];          // N*128, pre-scaled by inv_deg
__device__ __align__(16) float g_u[NN * 4];
__device__ __align__(16) float g_v[NN * 4];
__device__ __align__(16) __nv_bfloat16 g_w1h[65536];      // [256 out][256 k] hi
__device__ __align__(16) __nv_bfloat16 g_w1lo[65536];     // [256 out][256 k] lo

// ---------------- weight split + scratch reset (first launch each call) ----------------
__global__ void k_wsplit(const float* __restrict__ w1l, const float* __restrict__ w1r) {
    int idx = blockIdx.x * 256 + threadIdx.x;   // 65536 threads
    int out = idx >> 8, k = idx & 255;
    float v = (k < 128) ? w1l[out * 128 + k] : w1r[out * 128 + (k - 128)];
    __nv_bfloat16 h = __float2bfloat16(v);
    float r = v - __bfloat162float(h);
    g_w1h[idx]  = h;
    g_w1lo[idx] = __float2bfloat16(r);
    // reset histogram + lookback state (deterministic per call)
    for (int i = idx; i < NN; i += 65536) g_cnt[i] = 0;
    if (idx < 256) g_state[idx] = 0;
}

// ---------------- histogram of in-degrees ----------------
__global__ void k_hist(const int* __restrict__ ei) {
    int e = blockIdx.x * blockDim.x + threadIdx.x;
    if (e < EE) atomicAdd(&g_cnt[ei[EE + e]], 1);
}

// ---------------- single-kernel exclusive scan (decoupled lookback) ----------------
__global__ __launch_bounds__(512) void k_scan() {
    int b = blockIdx.x, t = threadIdx.x;
    int gid = b * 512 + t;
    int v = (gid < NN) ? g_cnt[gid] : 0;

    __shared__ int s[512];
    s[t] = v;
    for (int off = 1; off < 512; off <<= 1) {
        __syncthreads();
        int add = (t >= off) ? s[t - off] : 0;
        __syncthreads();
        s[t] += add;
    }
    __syncthreads();
    int incl  = s[t];
    int total = s[511];

    __shared__ int sExcl;
    if (t == 0) {
        if (b == 0) {
            atomicExch(&g_state[0], (2u << 30) | (unsigned)total);
            sExcl = 0;
        } else {
            atomicExch(&g_state[b], (1u << 30) | (unsigned)total);
            int excl = 0, j = b - 1;
            while (true) {
                unsigned st;
                do { st = atomicAdd(&g_state[j], 0u); } while ((st >> 30) == 0u);
                excl += (int)(st & 0x3FFFFFFFu);
                if ((st >> 30) == 2u) break;
                --j;
            }
            atomicExch(&g_state[b], (2u << 30) | (unsigned)(excl + total));
            sExcl = excl;
        }
    }
    __syncthreads();
    int rs = sExcl + incl - v;   // exclusive prefix
    if (gid < NN) { g_row_start[gid] = rs; g_cursor[gid] = rs; }
    if (gid == 0) g_row_start[NN] = EE;
}

// ---------------- CSR fill ----------------
__global__ void k_fill(const int* __restrict__ ei) {
    int e = blockIdx.x * blockDim.x + threadIdx.x;
    if (e < EE) {
        int d = ei[EE + e];
        int pos = atomicAdd(&g_cursor[d], 1);
        g_csr[pos] = ei[e];
    }
}

// ---------------- layer-1 mean aggregation (warp per node, gather, no atomics) ----------------
__global__ void k_agg1(const float* __restrict__ x) {
    int warp = threadIdx.x >> 5, lane = threadIdx.x & 31;
    int node = blockIdx.x * 8 + warp;
    if (node >= NN) return;
    int beg = g_row_start[node], end = g_row_start[node + 1];
    const float4* xv = (const float4*)x;
    float4 acc = make_float4(0.f, 0.f, 0.f, 0.f);
    int e = beg;
    for (; e + 3 < end; e += 4) {
        int s0 = g_csr[e], s1 = g_csr[e + 1], s2 = g_csr[e + 2], s3 = g_csr[e + 3];
        float4 t0 = xv[(size_t)s0 * 32 + lane];
        float4 t1 = xv[(size_t)s1 * 32 + lane];
        float4 t2 = xv[(size_t)s2 * 32 + lane];
        float4 t3 = xv[(size_t)s3 * 32 + lane];
        acc.x += (t0.x + t1.x) + (t2.x + t3.x);
        acc.y += (t0.y + t1.y) + (t2.y + t3.y);
        acc.z += (t0.z + t1.z) + (t2.z + t3.z);
        acc.w += (t0.w + t1.w) + (t2.w + t3.w);
    }
    for (; e < end; ++e) {
        int s0 = g_csr[e];
        float4 t0 = xv[(size_t)s0 * 32 + lane];
        acc.x += t0.x; acc.y += t0.y; acc.z += t0.z; acc.w += t0.w;
    }
    float inv = (end > beg) ? 1.0f / (float)(end - beg) : 0.f;
    acc.x *= inv; acc.y *= inv; acc.z *= inv; acc.w *= inv;
    ((float4*)g_aggx)[(size_t)node * 32 + lane] = acc;
}

// ---------------- helpers ----------------
__device__ __forceinline__ uint32_t smem_u32(const void* p) {
    uint32_t a;
    asm("{ .reg .u64 t; cvta.to.shared.u64 t, %1; cvt.u32.u64 %0, t; }" : "=r"(a) : "l"(p));
    return a;
}
__device__ __forceinline__ void ldm_x4(uint32_t* r, uint32_t addr) {
    asm volatile("ldmatrix.sync.aligned.m8n8.x4.shared.b16 {%0,%1,%2,%3}, [%4];"
                 : "=r"(r[0]), "=r"(r[1]), "=r"(r[2]), "=r"(r[3]) : "r"(addr));
}
__device__ __forceinline__ void ldm_x2(uint32_t* r, uint32_t addr) {
    asm volatile("ldmatrix.sync.aligned.m8n8.x2.shared.b16 {%0,%1}, [%2];"
                 : "=r"(r[0]), "=r"(r[1]) : "r"(addr));
}
__device__ __forceinline__ void mma_bf16(float* c, const uint32_t* a, const uint32_t* b) {
    asm volatile(
        "mma.sync.aligned.m16n8k16.row.col.f32.bf16.bf16.f32 "
        "{%0,%1,%2,%3}, {%4,%5,%6,%7}, {%8,%9}, {%0,%1,%2,%3};"
        : "+f"(c[0]), "+f"(c[1]), "+f"(c[2]), "+f"(c[3])
        : "r"(a[0]), "r"(a[1]), "r"(a[2]), "r"(a[3]), "r"(b[0]), "r"(b[1]));
}

// smem layout (bytes)
#define SA_HI 0            // [64][64] bf16 swizzled  (8 KB)
#define SA_LO 8192
#define SB_HI 16384        // [256][64] bf16 swizzled (32 KB)
#define SB_LO 49152
#define SM_W2 81920        // [8][256] f32 (8 KB)
#define SM_B1 90112        // [256] f32 (1 KB)
#define SM_TOT 91136
// h buffer [64][264] f32 = 67584 B reuses [0, 67584) after mainloop

// ---------------- mma.sync bf16-split GEMM + fused layer-2 projection ----------------
__global__ __launch_bounds__(256) void k_mma(
    const float* __restrict__ x, const float* __restrict__ b1,
    const float* __restrict__ w2l, const float* __restrict__ w2r)
{
    extern __shared__ char smem[];
    uint32_t sb = smem_u32(smem);
    int tid = threadIdx.x, wid = tid >> 5, lane = tid & 31;
    int rowBase = blockIdx.x * 64;

    // stage w2 (rows 0-3: w2l, 4-7: w2r) and b1
    {
        int o = tid >> 5, k = (tid & 31) * 8;
        const float* wp = (o < 4) ? (w2l + o * 256 + k) : (w2r + (o - 4) * 256 + k);
        *(float4*)(smem + SM_W2 + (size_t)(o * 256 + k) * 4)     = ((const float4*)wp)[0];
        *(float4*)(smem + SM_W2 + (size_t)(o * 256 + k + 4) * 4) = ((const float4*)wp)[1];
        if (tid < 64) *(float4*)(smem + SM_B1 + tid * 16) = ((const float4*)b1)[tid];
    }

    float C[4][4][4];
    #pragma unroll
    for (int mt = 0; mt < 4; ++mt)
        #pragma unroll
        for (int nt = 0; nt < 4; ++nt)
            #pragma unroll
            for (int q = 0; q < 4; ++q) C[mt][nt][q] = 0.f;

    int arow = tid >> 2, apart = tid & 3;      // A: 4 threads/row, 16 floats each
    int grow = rowBase + arow;

    for (int kc = 0; kc < 4; ++kc) {
        // ---- fetch globals to registers ----
        float av[16];
        {
            const float* src = (kc < 2) ? (g_aggx + (size_t)grow * 128 + kc * 64 + apart * 16)
                                        : (x      + (size_t)grow * 128 + (kc - 2) * 64 + apart * 16);
            if (grow < NN) {
                #pragma unroll
                for (int q = 0; q < 4; ++q) *(float4*)&av[q * 4] = ((const float4*)src)[q];
            } else {
                #pragma unroll
                for (int q = 0; q < 16; ++q) av[q] = 0.f;
            }
        }
        uint4 bh[8], bl[8];
        {
            const uint4* ph = (const uint4*)(g_w1h  + tid * 256 + kc * 64);
            const uint4* pl = (const uint4*)(g_w1lo + tid * 256 + kc * 64);
            #pragma unroll
            for (int q = 0; q < 8; ++q) { bh[q] = ph[q]; bl[q] = pl[q]; }
        }

        __syncthreads();

        // ---- store A hi/lo (swizzled 16B chunks) ----
        #pragma unroll
        for (int q = 0; q < 2; ++q) {
            int c = apart * 2 + q;
            union { __nv_bfloat162 h2[4]; uint4 u; } H, L;
            #pragma unroll
            for (int p = 0; p < 4; ++p) {
                float f0 = av[q * 8 + 2 * p], f1 = av[q * 8 + 2 * p + 1];
                __nv_bfloat16 h0 = __float2bfloat16(f0);
                __nv_bfloat16 h1 = __float2bfloat16(f1);
                H.h2[p] = __halves2bfloat162(h0, h1);
                L.h2[p] = __halves2bfloat162(
                    __float2bfloat16(f0 - __bfloat162float(h0)),
                    __float2bfloat16(f1 - __bfloat162float(h1)));
            }
            uint32_t byo = arow * 128 + ((c ^ (arow & 7)) << 4);
            *(uint4*)(smem + SA_HI + byo) = H.u;
            *(uint4*)(smem + SA_LO + byo) = L.u;
        }
        #pragma unroll
        for (int q = 0; q < 8; ++q) {
            uint32_t byo = tid * 128 + ((q ^ (tid & 7)) << 4);
            *(uint4*)(smem + SB_HI + byo) = bh[q];
            *(uint4*)(smem + SB_LO + byo) = bl[q];
        }
        __syncthreads();

        // ---- mma mainloop over 4 k16 steps ----
        #pragma unroll
        for (int ks = 0; ks < 4; ++ks) {
            uint32_t Ah[4][4], Al[4][4], Bh[4][2], Bl[4][2];
            int ar = lane & 15, ac = ks * 2 + (lane >> 4);
            #pragma unroll
            for (int mt = 0; mt < 4; ++mt) {
                int r = mt * 16 + ar;
                uint32_t byo = r * 128 + ((ac ^ (r & 7)) << 4);
                ldm_x4(Ah[mt], sb + SA_HI + byo);
                ldm_x4(Al[mt], sb + SA_LO + byo);
            }
            int br = lane & 7, bc = ks * 2 + ((lane >> 3) & 1);
            #pragma unroll
            for (int nt = 0; nt < 4; ++nt) {
                int r = wid * 32 + nt * 8 + br;
                uint32_t byo = r * 128 + ((bc ^ (r & 7)) << 4);
                ldm_x2(Bh[nt], sb + SB_HI + byo);
                ldm_x2(Bl[nt], sb + SB_LO + byo);
            }
            #pragma unroll
            for (int mt = 0; mt < 4; ++mt)
                #pragma unroll
                for (int nt = 0; nt < 4; ++nt) {
                    mma_bf16(C[mt][nt], Ah[mt], Bh[nt]);
                    mma_bf16(C[mt][nt], Ah[mt], Bl[nt]);
                    mma_bf16(C[mt][nt], Al[mt], Bh[nt]);
                }
        }
    }
    __syncthreads();

    // ---- epilogue: bias + relu -> smem h[64][264] ----
    float* hs  = (float*)smem;
    const float* b1s = (const float*)(smem + SM_B1);
    const float* w2s = (const float*)(smem + SM_W2);
    {
        int rq = lane >> 2, cq = (lane & 3) * 2;
        #pragma unroll
        for (int mt = 0; mt < 4; ++mt)
            #pragma unroll
            for (int nt = 0; nt < 4; ++nt) {
                int col = wid * 32 + nt * 8 + cq;
                float bx = b1s[col], by = b1s[col + 1];
                int r0 = mt * 16 + rq, r1 = r0 + 8;
                float v00 = C[mt][nt][0] + bx, v01 = C[mt][nt][1] + by;
                float v10 = C[mt][nt][2] + bx, v11 = C[mt][nt][3] + by;
                *(float2*)&hs[r0 * 264 + col] =
                    make_float2(v00 > 0.f ? v00 : 0.f, v01 > 0.f ? v01 : 0.f);
                *(float2*)&hs[r1 * 264 + col] =
                    make_float2(v10 > 0.f ? v10 : 0.f, v11 > 0.f ? v11 : 0.f);
            }
    }
    __syncthreads();

    // ---- layer-2 projection: warp per 8 rows ----
    #pragma unroll
    for (int rr = 0; rr < 8; ++rr) {
        int row = wid * 8 + rr;
        const float* hr = &hs[row * 264];
        float4 p0 = *(const float4*)&hr[lane * 8];
        float4 p1 = *(const float4*)&hr[lane * 8 + 4];
        float val = 0.f;
        #pragma unroll
        for (int o = 0; o < 8; ++o) {
            const float* wr = &w2s[o * 256 + lane * 8];
            float s = p0.x * wr[0] + p0.y * wr[1] + p0.z * wr[2] + p0.w * wr[3]
                    + p1.x * wr[4] + p1.y * wr[5] + p1.z * wr[6] + p1.w * wr[7];
            #pragma unroll
            for (int off = 16; off; off >>= 1) s += __shfl_xor_sync(FULL, s, off);
            if (lane == o) val = s;
        }
        int gr = rowBase + row;
        if (gr < NN) {
            if (lane < 4)      g_u[gr * 4 + lane]       = val;
            else if (lane < 8) g_v[gr * 4 + (lane - 4)] = val;
        }
    }
}

// ---------------- layer-2 aggregation + bias + residual + log_softmax ----------------
__global__ void k_final(const float* __restrict__ b2, float* __restrict__ out) {
    int warp = threadIdx.x >> 5, lane = threadIdx.x & 31;
    int node = blockIdx.x * 8 + warp;
    if (node >= NN) return;
    int beg = g_row_start[node], end = g_row_start[node + 1];
    int ei8 = lane >> 2, c = lane & 3;
    float acc = 0.f;
    for (int base = beg; base < end; base += 8) {
        int e = base + ei8;
        if (e < end) {
            int s = g_csr[e];
            acc += g_u[s * 4 + c];
        }
    }
    acc += __shfl_down_sync(FULL, acc, 16);
    acc += __shfl_down_sync(FULL, acc, 8);
    acc += __shfl_down_sync(FULL, acc, 4);
    float inv = (end > beg) ? 1.0f / (float)(end - beg) : 0.f;
    float val = acc * inv + b2[c] + g_v[node * 4 + c];
    float m = val;
    m = fmaxf(m, __shfl_xor_sync(FULL, m, 1));
    m = fmaxf(m, __shfl_xor_sync(FULL, m, 2));
    float ex = expf(val - m);
    float ssum = ex;
    ssum += __shfl_xor_sync(FULL, ssum, 1);
    ssum += __shfl_xor_sync(FULL, ssum, 2);
    if (lane < 4) out[node * 4 + c] = val - m - logf(ssum);
}

// ---------------- eager module load + smem opt-in (static init, outside capture) ----------------
namespace {
struct HXModuleLoad {
    HXModuleLoad() {
        cudaFuncAttributes a;
        (void)cudaFuncGetAttributes(&a, (const void*)k_hist);
        (void)cudaFuncSetAttribute((const void*)k_mma,
                                   cudaFuncAttributeMaxDynamicSharedMemorySize, SM_TOT);
    }
};
HXModuleLoad hx_module_load_;
}

// ---------------- launch ----------------
extern "C" void kernel_launch(void* const* d_in, const int* in_sizes, int n_in,
                              void* d_out, int out_size) {
    const float* x   = (const float*)d_in[0];
    const int*   ei  = (const int*)d_in[1];   // int32 edge_index: [0..E)=src, [E..2E)=dst
    const float* w1l = (const float*)d_in[2];
    const float* w1r = (const float*)d_in[3];
    const float* b1  = (const float*)d_in[4];
    const float* w2l = (const float*)d_in[5];
    const float* w2r = (const float*)d_in[6];
    const float* b2  = (const float*)d_in[7];
    float* out = (float*)d_out;

    k_wsplit<<<256, 256>>>(w1l, w1r);                 // 1: also zeroes g_cnt/g_state
    k_hist<<<(EE + 511) / 512, 512>>>(ei);            // 2
    k_scan<<<NB_SCAN, 512>>>();                       // 3: single-pass lookback scan
    k_fill<<<(EE + 255) / 256, 256>>>(ei);            // 4
    k_agg1<<<(NN + 7) / 8, 256>>>(x);                 // 5
    k_mma<<<(NN + 63) / 64, 256, SM_TOT>>>(x, b1, w2l, w2r);  // 6  <- ncu -s 5 lands here
    k_final<<<(NN + 7) / 8, 256>>>(b2, out);          // 7
}

// round 9
// speedup vs baseline: 1.1251x; 1.1251x over previous
#include <cuda_runtime.h>
#include <cuda_bf16.h>
#include <cstdint>

#define NN 100000
#define EE 1600000
#define FULL 0xffffffffu
#define NB_SCAN 196

// ---------------- scratch (static device globals; no allocation) ----------------
__device__ __align__(16) int   g_cnt[NN];
__device__ __align__(16) int   g_row_start[NN + 1];
__device__ __align__(16) int   g_cursor[NN];
__device__ __align__(16) int   g_csr[EE];
__device__ __align__(16) unsigned int g_state[256];       // lookback: flag(2b)|value(30b)
__device__ __align__(16) float g_aggx[12800000];          // N*128, pre-scaled by inv_deg
__device__ __align__(16) float g_u[NN * 4];
__device__ __align__(16) float g_v[NN * 4];
__device__ __align__(16) __nv_bfloat16 g_w1h[65536];      // [256 out][256 k] hi
__device__ __align__(16) __nv_bfloat16 g_w1lo[65536];     // [256 out][256 k] lo

// ---------------- weight split + scratch reset (first launch each call) ----------------
__global__ void k_wsplit(const float* __restrict__ w1l, const float* __restrict__ w1r) {
    int idx = blockIdx.x * 256 + threadIdx.x;   // 65536 threads
    int out = idx >> 8, k = idx & 255;
    float v = (k < 128) ? w1l[out * 128 + k] : w1r[out * 128 + (k - 128)];
    __nv_bfloat16 h = __float2bfloat16(v);
    float r = v - __bfloat162float(h);
    g_w1h[idx]  = h;
    g_w1lo[idx] = __float2bfloat16(r);
    // reset histogram + lookback state (deterministic per call)
    for (int i = idx; i < NN; i += 65536) g_cnt[i] = 0;
    if (idx < 256) g_state[idx] = 0;
}

// ---------------- histogram of in-degrees ----------------
__global__ void k_hist(const int* __restrict__ ei) {
    int e = blockIdx.x * blockDim.x + threadIdx.x;
    if (e < EE) atomicAdd(&g_cnt[ei[EE + e]], 1);
}

// ---------------- single-kernel exclusive scan (decoupled lookback) ----------------
__global__ __launch_bounds__(512) void k_scan() {
    int b = blockIdx.x, t = threadIdx.x;
    int gid = b * 512 + t;
    int v = (gid < NN) ? g_cnt[gid] : 0;

    __shared__ int s[512];
    s[t] = v;
    for (int off = 1; off < 512; off <<= 1) {
        __syncthreads();
        int add = (t >= off) ? s[t - off] : 0;
        __syncthreads();
        s[t] += add;
    }
    __syncthreads();
    int incl  = s[t];
    int total = s[511];

    __shared__ int sExcl;
    if (t == 0) {
        if (b == 0) {
            atomicExch(&g_state[0], (2u << 30) | (unsigned)total);
            sExcl = 0;
        } else {
            atomicExch(&g_state[b], (1u << 30) | (unsigned)total);
            int excl = 0, j = b - 1;
            while (true) {
                unsigned st;
                do { st = atomicAdd(&g_state[j], 0u); } while ((st >> 30) == 0u);
                excl += (int)(st & 0x3FFFFFFFu);
                if ((st >> 30) == 2u) break;
                --j;
            }
            atomicExch(&g_state[b], (2u << 30) | (unsigned)(excl + total));
            sExcl = excl;
        }
    }
    __syncthreads();
    int rs = sExcl + incl - v;   // exclusive prefix
    if (gid < NN) { g_row_start[gid] = rs; g_cursor[gid] = rs; }
    if (gid == 0) g_row_start[NN] = EE;
}

// ---------------- CSR fill ----------------
__global__ void k_fill(const int* __restrict__ ei) {
    int e = blockIdx.x * blockDim.x + threadIdx.x;
    if (e < EE) {
        int d = ei[EE + e];
        int pos = atomicAdd(&g_cursor[d], 1);
        g_csr[pos] = ei[e];
    }
}

// ---------------- layer-1 mean aggregation (warp per node, gather, no atomics) ----------------
__global__ void k_agg1(const float* __restrict__ x) {
    int warp = threadIdx.x >> 5, lane = threadIdx.x & 31;
    int node = blockIdx.x * 8 + warp;
    if (node >= NN) return;
    int beg = g_row_start[node], end = g_row_start[node + 1];
    const float4* xv = (const float4*)x;
    float4 acc = make_float4(0.f, 0.f, 0.f, 0.f);
    int e = beg;
    for (; e + 3 < end; e += 4) {
        int s0 = g_csr[e], s1 = g_csr[e + 1], s2 = g_csr[e + 2], s3 = g_csr[e + 3];
        float4 t0 = xv[(size_t)s0 * 32 + lane];
        float4 t1 = xv[(size_t)s1 * 32 + lane];
        float4 t2 = xv[(size_t)s2 * 32 + lane];
        float4 t3 = xv[(size_t)s3 * 32 + lane];
        acc.x += (t0.x + t1.x) + (t2.x + t3.x);
        acc.y += (t0.y + t1.y) + (t2.y + t3.y);
        acc.z += (t0.z + t1.z) + (t2.z + t3.z);
        acc.w += (t0.w + t1.w) + (t2.w + t3.w);
    }
    for (; e < end; ++e) {
        int s0 = g_csr[e];
        float4 t0 = xv[(size_t)s0 * 32 + lane];
        acc.x += t0.x; acc.y += t0.y; acc.z += t0.z; acc.w += t0.w;
    }
    float inv = (end > beg) ? 1.0f / (float)(end - beg) : 0.f;
    acc.x *= inv; acc.y *= inv; acc.z *= inv; acc.w *= inv;
    ((float4*)g_aggx)[(size_t)node * 32 + lane] = acc;
}

// ---------------- helpers ----------------
__device__ __forceinline__ uint32_t smem_u32(const void* p) {
    uint32_t a;
    asm("{ .reg .u64 t; cvta.to.shared.u64 t, %1; cvt.u32.u64 %0, t; }" : "=r"(a) : "l"(p));
    return a;
}
__device__ __forceinline__ void ldm_x4(uint32_t* r, uint32_t addr) {
    asm volatile("ldmatrix.sync.aligned.m8n8.x4.shared.b16 {%0,%1,%2,%3}, [%4];"
                 : "=r"(r[0]), "=r"(r[1]), "=r"(r[2]), "=r"(r[3]) : "r"(addr));
}
__device__ __forceinline__ void ldm_x2(uint32_t* r, uint32_t addr) {
    asm volatile("ldmatrix.sync.aligned.m8n8.x2.shared.b16 {%0,%1}, [%2];"
                 : "=r"(r[0]), "=r"(r[1]) : "r"(addr));
}
__device__ __forceinline__ void mma_bf16(float* c, const uint32_t* a, const uint32_t* b) {
    asm volatile(
        "mma.sync.aligned.m16n8k16.row.col.f32.bf16.bf16.f32 "
        "{%0,%1,%2,%3}, {%4,%5,%6,%7}, {%8,%9}, {%0,%1,%2,%3};"
        : "+f"(c[0]), "+f"(c[1]), "+f"(c[2]), "+f"(c[3])
        : "r"(a[0]), "r"(a[1]), "r"(a[2]), "r"(a[3]), "r"(b[0]), "r"(b[1]));
}
__device__ __forceinline__ void cp16(uint32_t smem_addr, const void* gptr) {
    asm volatile("cp.async.cg.shared.global [%0], [%1], 16;"
                 :: "r"(smem_addr), "l"(gptr) : "memory");
}
__device__ __forceinline__ void cp_commit() {
    asm volatile("cp.async.commit_group;" ::: "memory");
}
__device__ __forceinline__ void cp_wait0() {
    asm volatile("cp.async.wait_group 0;" ::: "memory");
}

// smem layout (bytes) — double-buffered A/B tiles
#define SA_HI 0            // 2 x [64][64] bf16 swizzled   (2 x 8 KB)
#define SA_LO 16384        // 2 x 8 KB
#define SB_HI 32768        // 2 x [256][64] bf16 swizzled  (2 x 32 KB)
#define SB_LO 98304        // 2 x 32 KB
#define SM_W2 163840       // [8][256] f32 (8 KB)
#define SM_B1 172032       // [256] f32 (1 KB)
#define SM_TOT 173056
// h buffer [64][264] f32 = 67584 B reuses [0, 67584) after mainloop

// ---------------- mma.sync bf16-split GEMM + fused layer-2 projection ----------------
// Per CTA: rows rowBase..rowBase+63, all 256 output cols. 8 warps, warp tile 64x32.
// D = Ah*Wh + Ah*Wl + Al*Wh (fp32 accum). cp.async double-buffered B, reg double-buffered A.
__global__ __launch_bounds__(256) void k_mma(
    const float* __restrict__ x, const float* __restrict__ b1,
    const float* __restrict__ w2l, const float* __restrict__ w2r)
{
    extern __shared__ char smem[];
    uint32_t sb = smem_u32(smem);
    int tid = threadIdx.x, wid = tid >> 5, lane = tid & 31;
    int rowBase = blockIdx.x * 64;

    int arow = tid >> 2, apart = tid & 3;      // A: 4 threads/row, 16 floats each
    int grow = rowBase + arow;

    // B cp.async issue helper (row = tid, 8 hi + 8 lo 16B chunks)
    auto issueB = [&](int kc, int buf) {
        uint32_t dhi = sb + SB_HI + buf * 32768 + tid * 128;
        uint32_t dlo = sb + SB_LO + buf * 32768 + tid * 128;
        const __nv_bfloat16* ph = g_w1h  + tid * 256 + kc * 64;
        const __nv_bfloat16* pl = g_w1lo + tid * 256 + kc * 64;
        #pragma unroll
        for (int q = 0; q < 8; ++q) {
            uint32_t sw = (uint32_t)((q ^ (tid & 7)) << 4);
            cp16(dhi + sw, ph + q * 8);
            cp16(dlo + sw, pl + q * 8);
        }
    };
    auto ldgA = [&](int kc, float* av) {
        const float* src = (kc < 2) ? (g_aggx + (size_t)grow * 128 + kc * 64 + apart * 16)
                                    : (x      + (size_t)grow * 128 + (kc - 2) * 64 + apart * 16);
        if (grow < NN) {
            #pragma unroll
            for (int q = 0; q < 4; ++q) *(float4*)&av[q * 4] = ((const float4*)src)[q];
        } else {
            #pragma unroll
            for (int q = 0; q < 16; ++q) av[q] = 0.f;
        }
    };

    // ---- prologue: kick off chunk 0 loads, stage w2/b1 ----
    float av[2][16];
    issueB(0, 0);
    cp_commit();
    ldgA(0, av[0]);
    {
        int o = tid >> 5, k = (tid & 31) * 8;
        const float* wp = (o < 4) ? (w2l + o * 256 + k) : (w2r + (o - 4) * 256 + k);
        *(float4*)(smem + SM_W2 + (size_t)(o * 256 + k) * 4)     = ((const float4*)wp)[0];
        *(float4*)(smem + SM_W2 + (size_t)(o * 256 + k + 4) * 4) = ((const float4*)wp)[1];
        if (tid < 64) *(float4*)(smem + SM_B1 + tid * 16) = ((const float4*)b1)[tid];
    }

    float C[4][4][4];
    #pragma unroll
    for (int mt = 0; mt < 4; ++mt)
        #pragma unroll
        for (int nt = 0; nt < 4; ++nt)
            #pragma unroll
            for (int q = 0; q < 4; ++q) C[mt][nt][q] = 0.f;

    #pragma unroll
    for (int kc = 0; kc < 4; ++kc) {
        int buf = kc & 1;
        cp_wait0();   // B[kc] landed in smem

        // ---- convert + store A[kc] hi/lo (swizzled 16B chunks) ----
        #pragma unroll
        for (int q = 0; q < 2; ++q) {
            int c = apart * 2 + q;
            union { __nv_bfloat162 h2[4]; uint4 u; } H, L;
            #pragma unroll
            for (int p = 0; p < 4; ++p) {
                float f0 = av[buf][q * 8 + 2 * p], f1 = av[buf][q * 8 + 2 * p + 1];
                __nv_bfloat16 h0 = __float2bfloat16(f0);
                __nv_bfloat16 h1 = __float2bfloat16(f1);
                H.h2[p] = __halves2bfloat162(h0, h1);
                L.h2[p] = __halves2bfloat162(
                    __float2bfloat16(f0 - __bfloat162float(h0)),
                    __float2bfloat16(f1 - __bfloat162float(h1)));
            }
            uint32_t byo = buf * 8192 + arow * 128 + ((c ^ (arow & 7)) << 4);
            *(uint4*)(smem + SA_HI + byo) = H.u;
            *(uint4*)(smem + SA_LO + byo) = L.u;
        }
        __syncthreads();   // A[kc] + B[kc] visible to all; prior-buf reads done (skew < 1 iter)

        // ---- launch next chunk's loads (overlap with MMA below) ----
        if (kc < 3) {
            issueB(kc + 1, buf ^ 1);
            cp_commit();
            ldgA(kc + 1, av[buf ^ 1]);
        }

        // ---- mma over 4 k16 steps on buffer `buf` ----
        uint32_t baseAH = sb + SA_HI + buf * 8192;
        uint32_t baseAL = sb + SA_LO + buf * 8192;
        uint32_t baseBH = sb + SB_HI + buf * 32768;
        uint32_t baseBL = sb + SB_LO + buf * 32768;
        #pragma unroll
        for (int ks = 0; ks < 4; ++ks) {
            uint32_t Ah[4][4], Al[4][4], Bh[4][2], Bl[4][2];
            int ar = lane & 15, ac = ks * 2 + (lane >> 4);
            #pragma unroll
            for (int mt = 0; mt < 4; ++mt) {
                int r = mt * 16 + ar;
                uint32_t byo = r * 128 + ((ac ^ (r & 7)) << 4);
                ldm_x4(Ah[mt], baseAH + byo);
                ldm_x4(Al[mt], baseAL + byo);
            }
            int br = lane & 7, bc = ks * 2 + ((lane >> 3) & 1);
            #pragma unroll
            for (int nt = 0; nt < 4; ++nt) {
                int r = wid * 32 + nt * 8 + br;
                uint32_t byo = r * 128 + ((bc ^ (r & 7)) << 4);
                ldm_x2(Bh[nt], baseBH + byo);
                ldm_x2(Bl[nt], baseBL + byo);
            }
            #pragma unroll
            for (int mt = 0; mt < 4; ++mt)
                #pragma unroll
                for (int nt = 0; nt < 4; ++nt) {
                    mma_bf16(C[mt][nt], Ah[mt], Bh[nt]);
                    mma_bf16(C[mt][nt], Ah[mt], Bl[nt]);
                    mma_bf16(C[mt][nt], Al[mt], Bh[nt]);
                }
        }
    }
    __syncthreads();   // all frag reads done; tile smem reusable as h buffer

    // ---- epilogue: bias + relu -> smem h[64][264] ----
    float* hs  = (float*)smem;
    const float* b1s = (const float*)(smem + SM_B1);
    const float* w2s = (const float*)(smem + SM_W2);
    {
        int rq = lane >> 2, cq = (lane & 3) * 2;
        #pragma unroll
        for (int mt = 0; mt < 4; ++mt)
            #pragma unroll
            for (int nt = 0; nt < 4; ++nt) {
                int col = wid * 32 + nt * 8 + cq;
                float bx = b1s[col], by = b1s[col + 1];
                int r0 = mt * 16 + rq, r1 = r0 + 8;
                float v00 = C[mt][nt][0] + bx, v01 = C[mt][nt][1] + by;
                float v10 = C[mt][nt][2] + bx, v11 = C[mt][nt][3] + by;
                *(float2*)&hs[r0 * 264 + col] =
                    make_float2(v00 > 0.f ? v00 : 0.f, v01 > 0.f ? v01 : 0.f);
                *(float2*)&hs[r1 * 264 + col] =
                    make_float2(v10 > 0.f ? v10 : 0.f, v11 > 0.f ? v11 : 0.f);
            }
    }
    __syncthreads();

    // ---- layer-2 projection: warp per 8 rows ----
    #pragma unroll
    for (int rr = 0; rr < 8; ++rr) {
        int row = wid * 8 + rr;
        const float* hr = &hs[row * 264];
        float4 p0 = *(const float4*)&hr[lane * 8];
        float4 p1 = *(const float4*)&hr[lane * 8 + 4];
        float val = 0.f;
        #pragma unroll
        for (int o = 0; o < 8; ++o) {
            const float* wr = &w2s[o * 256 + lane * 8];
            float s = p0.x * wr[0] + p0.y * wr[1] + p0.z * wr[2] + p0.w * wr[3]
                    + p1.x * wr[4] + p1.y * wr[5] + p1.z * wr[6] + p1.w * wr[7];
            #pragma unroll
            for (int off = 16; off; off >>= 1) s += __shfl_xor_sync(FULL, s, off);
            if (lane == o) val = s;
        }
        int gr = rowBase + row;
        if (gr < NN) {
            if (lane < 4)      g_u[gr * 4 + lane]       = val;
            else if (lane < 8) g_v[gr * 4 + (lane - 4)] = val;
        }
    }
}

// ---------------- layer-2 aggregation + bias + residual + log_softmax ----------------
__global__ void k_final(const float* __restrict__ b2, float* __restrict__ out) {
    int warp = threadIdx.x >> 5, lane = threadIdx.x & 31;
    int node = blockIdx.x * 8 + warp;
    if (node >= NN) return;
    int beg = g_row_start[node], end = g_row_start[node + 1];
    int ei8 = lane >> 2, c = lane & 3;
    float acc = 0.f;
    for (int base = beg; base < end; base += 8) {
        int e = base + ei8;
        if (e < end) {
            int s = g_csr[e];
            acc += g_u[s * 4 + c];
        }
    }
    acc += __shfl_down_sync(FULL, acc, 16);
    acc += __shfl_down_sync(FULL, acc, 8);
    acc += __shfl_down_sync(FULL, acc, 4);
    float inv = (end > beg) ? 1.0f / (float)(end - beg) : 0.f;
    float val = acc * inv + b2[c] + g_v[node * 4 + c];
    float m = val;
    m = fmaxf(m, __shfl_xor_sync(FULL, m, 1));
    m = fmaxf(m, __shfl_xor_sync(FULL, m, 2));
    float ex = expf(val - m);
    float ssum = ex;
    ssum += __shfl_xor_sync(FULL, ssum, 1);
    ssum += __shfl_xor_sync(FULL, ssum, 2);
    if (lane < 4) out[node * 4 + c] = val - m - logf(ssum);
}

// ---------------- eager module load + smem opt-in (static init, outside capture) ----------------
namespace {
struct HXModuleLoad {
    HXModuleLoad() {
        cudaFuncAttributes a;
        (void)cudaFuncGetAttributes(&a, (const void*)k_hist);
        (void)cudaFuncSetAttribute((const void*)k_mma,
                                   cudaFuncAttributeMaxDynamicSharedMemorySize, SM_TOT);
    }
};
HXModuleLoad hx_module_load_;
}

// ---------------- launch ----------------
extern "C" void kernel_launch(void* const* d_in, const int* in_sizes, int n_in,
                              void* d_out, int out_size) {
    const float* x   = (const float*)d_in[0];
    const int*   ei  = (const int*)d_in[1];   // int32 edge_index: [0..E)=src, [E..2E)=dst
    const float* w1l = (const float*)d_in[2];
    const float* w1r = (const float*)d_in[3];
    const float* b1  = (const float*)d_in[4];
    const float* w2l = (const float*)d_in[5];
    const float* w2r = (const float*)d_in[6];
    const float* b2  = (const float*)d_in[7];
    float* out = (float*)d_out;

    k_wsplit<<<256, 256>>>(w1l, w1r);                 // 1: also zeroes g_cnt/g_state
    k_hist<<<(EE + 511) / 512, 512>>>(ei);            // 2
    k_scan<<<NB_SCAN, 512>>>();                       // 3: single-pass lookback scan
    k_fill<<<(EE + 255) / 256, 256>>>(ei);            // 4
    k_agg1<<<(NN + 7) / 8, 256>>>(x);                 // 5
    k_mma<<<(NN + 63) / 64, 256, SM_TOT>>>(x, b1, w2l, w2r);  // 6
    k_final<<<(NN + 7) / 8, 256>>>(b2, out);          // 7
}

// round 10
// speedup vs baseline: 1.1838x; 1.0521x over previous
#include <cuda_runtime.h>
#include <cuda_fp16.h>
#include <cstdint>

#define NN 100000
#define EE 1600000
#define FULL 0xffffffffu
#define NB_SCAN 196

// ---------------- scratch (static device globals; no allocation) ----------------
__device__ __align__(16) int   g_cnt[NN];
__device__ __align__(16) int   g_row_start[NN + 1];
__device__ __align__(16) int   g_cursor[NN];
__device__ __align__(16) int   g_csr[EE];
__device__ __align__(16) unsigned int g_state[256];       // lookback: flag(2b)|value(30b)
__device__ __align__(16) float g_aggx[12800000];          // N*128, pre-scaled by inv_deg
__device__ __align__(16) float g_u[NN * 4];
__device__ __align__(16) float g_v[NN * 4];
__device__ __align__(16) __half g_w1h[65536];             // [256 out][256 k] fp16 hi
__device__ __align__(16) __half g_w1lo[65536];            // [256 out][256 k] fp16 lo

// ---------------- weight split + scratch reset (first launch each call) ----------------
__global__ void k_wsplit(const float* __restrict__ w1l, const float* __restrict__ w1r) {
    int idx = blockIdx.x * 256 + threadIdx.x;   // 65536 threads
    int out = idx >> 8, k = idx & 255;
    float v = (k < 128) ? w1l[out * 128 + k] : w1r[out * 128 + (k - 128)];
    __half h = __float2half_rn(v);
    float r = v - __half2float(h);
    g_w1h[idx]  = h;
    g_w1lo[idx] = __float2half_rn(r);
    // reset histogram + lookback state (deterministic per call)
    for (int i = idx; i < NN; i += 65536) g_cnt[i] = 0;
    if (idx < 256) g_state[idx] = 0;
}

// ---------------- histogram of in-degrees ----------------
__global__ void k_hist(const int* __restrict__ ei) {
    int e = blockIdx.x * blockDim.x + threadIdx.x;
    if (e < EE) atomicAdd(&g_cnt[ei[EE + e]], 1);
}

// ---------------- single-kernel exclusive scan (decoupled lookback) ----------------
__global__ __launch_bounds__(512) void k_scan() {
    int b = blockIdx.x, t = threadIdx.x;
    int gid = b * 512 + t;
    int v = (gid < NN) ? g_cnt[gid] : 0;

    __shared__ int s[512];
    s[t] = v;
    for (int off = 1; off < 512; off <<= 1) {
        __syncthreads();
        int add = (t >= off) ? s[t - off] : 0;
        __syncthreads();
        s[t] += add;
    }
    __syncthreads();
    int incl  = s[t];
    int total = s[511];

    __shared__ int sExcl;
    if (t == 0) {
        if (b == 0) {
            atomicExch(&g_state[0], (2u << 30) | (unsigned)total);
            sExcl = 0;
        } else {
            atomicExch(&g_state[b], (1u << 30) | (unsigned)total);
            int excl = 0, j = b - 1;
            while (true) {
                unsigned st;
                do { st = atomicAdd(&g_state[j], 0u); } while ((st >> 30) == 0u);
                excl += (int)(st & 0x3FFFFFFFu);
                if ((st >> 30) == 2u) break;
                --j;
            }
            atomicExch(&g_state[b], (2u << 30) | (unsigned)(excl + total));
            sExcl = excl;
        }
    }
    __syncthreads();
    int rs = sExcl + incl - v;   // exclusive prefix
    if (gid < NN) { g_row_start[gid] = rs; g_cursor[gid] = rs; }
    if (gid == 0) g_row_start[NN] = EE;
}

// ---------------- CSR fill ----------------
__global__ void k_fill(const int* __restrict__ ei) {
    int e = blockIdx.x * blockDim.x + threadIdx.x;
    if (e < EE) {
        int d = ei[EE + e];
        int pos = atomicAdd(&g_cursor[d], 1);
        g_csr[pos] = ei[e];
    }
}

// ---------------- layer-1 mean aggregation (warp per node, gather, no atomics) ----------------
__global__ void k_agg1(const float* __restrict__ x) {
    int warp = threadIdx.x >> 5, lane = threadIdx.x & 31;
    int node = blockIdx.x * 8 + warp;
    if (node >= NN) return;
    int beg = g_row_start[node], end = g_row_start[node + 1];
    const float4* xv = (const float4*)x;
    float4 acc = make_float4(0.f, 0.f, 0.f, 0.f);
    int e = beg;
    for (; e + 3 < end; e += 4) {
        int s0 = g_csr[e], s1 = g_csr[e + 1], s2 = g_csr[e + 2], s3 = g_csr[e + 3];
        float4 t0 = xv[(size_t)s0 * 32 + lane];
        float4 t1 = xv[(size_t)s1 * 32 + lane];
        float4 t2 = xv[(size_t)s2 * 32 + lane];
        float4 t3 = xv[(size_t)s3 * 32 + lane];
        acc.x += (t0.x + t1.x) + (t2.x + t3.x);
        acc.y += (t0.y + t1.y) + (t2.y + t3.y);
        acc.z += (t0.z + t1.z) + (t2.z + t3.z);
        acc.w += (t0.w + t1.w) + (t2.w + t3.w);
    }
    for (; e < end; ++e) {
        int s0 = g_csr[e];
        float4 t0 = xv[(size_t)s0 * 32 + lane];
        acc.x += t0.x; acc.y += t0.y; acc.z += t0.z; acc.w += t0.w;
    }
    float inv = (end > beg) ? 1.0f / (float)(end - beg) : 0.f;
    acc.x *= inv; acc.y *= inv; acc.z *= inv; acc.w *= inv;
    ((float4*)g_aggx)[(size_t)node * 32 + lane] = acc;
}

// ---------------- helpers ----------------
__device__ __forceinline__ uint32_t smem_u32(const void* p) {
    uint32_t a;
    asm("{ .reg .u64 t; cvta.to.shared.u64 t, %1; cvt.u32.u64 %0, t; }" : "=r"(a) : "l"(p));
    return a;
}
__device__ __forceinline__ void ldm_x4(uint32_t* r, uint32_t addr) {
    asm volatile("ldmatrix.sync.aligned.m8n8.x4.shared.b16 {%0,%1,%2,%3}, [%4];"
                 : "=r"(r[0]), "=r"(r[1]), "=r"(r[2]), "=r"(r[3]) : "r"(addr));
}
__device__ __forceinline__ void ldm_x2(uint32_t* r, uint32_t addr) {
    asm volatile("ldmatrix.sync.aligned.m8n8.x2.shared.b16 {%0,%1}, [%2];"
                 : "=r"(r[0]), "=r"(r[1]) : "r"(addr));
}
__device__ __forceinline__ void mma_f16(float* c, const uint32_t* a, const uint32_t* b) {
    asm volatile(
        "mma.sync.aligned.m16n8k16.row.col.f32.f16.f16.f32 "
        "{%0,%1,%2,%3}, {%4,%5,%6,%7}, {%8,%9}, {%0,%1,%2,%3};"
        : "+f"(c[0]), "+f"(c[1]), "+f"(c[2]), "+f"(c[3])
        : "r"(a[0]), "r"(a[1]), "r"(a[2]), "r"(a[3]), "r"(b[0]), "r"(b[1]));
}
__device__ __forceinline__ void cp16(uint32_t smem_addr, const void* gptr) {
    asm volatile("cp.async.cg.shared.global [%0], [%1], 16;"
                 :: "r"(smem_addr), "l"(gptr) : "memory");
}
__device__ __forceinline__ void cp_commit() {
    asm volatile("cp.async.commit_group;" ::: "memory");
}
__device__ __forceinline__ void cp_wait0() {
    asm volatile("cp.async.wait_group 0;" ::: "memory");
}

// smem layout (bytes) — double-buffered A/B tiles (fp16)
#define SA    0            // 2 x [64][64] f16 swizzled    (2 x 8 KB)
#define SB_HI 16384        // 2 x [256][64] f16 swizzled   (2 x 32 KB)
#define SB_LO 81920        // 2 x 32 KB
#define SM_W2 147456       // [8][256] f32 (8 KB)
#define SM_B1 155648       // [256] f32 (1 KB)
#define SM_TOT 156672
// h buffer [64][264] f32 = 67584 B reuses [0, 67584) after mainloop

// ---------------- mma.sync fp16 2-term GEMM + fused layer-2 projection ----------------
// Per CTA: rows rowBase..rowBase+63, all 256 output cols. 8 warps, warp tile 64x32.
// D = Ah*Wh + Ah*Wl (fp16 inputs, fp32 accum; dropped Al*W ~ 2^-11 rel).
__global__ __launch_bounds__(256) void k_mma(
    const float* __restrict__ x, const float* __restrict__ b1,
    const float* __restrict__ w2l, const float* __restrict__ w2r)
{
    extern __shared__ char smem[];
    uint32_t sb = smem_u32(smem);
    int tid = threadIdx.x, wid = tid >> 5, lane = tid & 31;
    int rowBase = blockIdx.x * 64;

    int arow = tid >> 2, apart = tid & 3;      // A: 4 threads/row, 16 floats each
    int grow = rowBase + arow;

    // B cp.async issue helper (row = tid, 8 hi + 8 lo 16B chunks)
    auto issueB = [&](int kc, int buf) {
        uint32_t dhi = sb + SB_HI + buf * 32768 + tid * 128;
        uint32_t dlo = sb + SB_LO + buf * 32768 + tid * 128;
        const __half* ph = g_w1h  + tid * 256 + kc * 64;
        const __half* pl = g_w1lo + tid * 256 + kc * 64;
        #pragma unroll
        for (int q = 0; q < 8; ++q) {
            uint32_t sw = (uint32_t)((q ^ (tid & 7)) << 4);
            cp16(dhi + sw, ph + q * 8);
            cp16(dlo + sw, pl + q * 8);
        }
    };
    auto ldgA = [&](int kc, float* av) {
        const float* src = (kc < 2) ? (g_aggx + (size_t)grow * 128 + kc * 64 + apart * 16)
                                    : (x      + (size_t)grow * 128 + (kc - 2) * 64 + apart * 16);
        if (grow < NN) {
            #pragma unroll
            for (int q = 0; q < 4; ++q) *(float4*)&av[q * 4] = ((const float4*)src)[q];
        } else {
            #pragma unroll
            for (int q = 0; q < 16; ++q) av[q] = 0.f;
        }
    };

    // ---- prologue: kick off chunk 0 loads, stage w2/b1 ----
    float av[2][16];
    issueB(0, 0);
    cp_commit();
    ldgA(0, av[0]);
    {
        int o = tid >> 5, k = (tid & 31) * 8;
        const float* wp = (o < 4) ? (w2l + o * 256 + k) : (w2r + (o - 4) * 256 + k);
        *(float4*)(smem + SM_W2 + (size_t)(o * 256 + k) * 4)     = ((const float4*)wp)[0];
        *(float4*)(smem + SM_W2 + (size_t)(o * 256 + k + 4) * 4) = ((const float4*)wp)[1];
        if (tid < 64) *(float4*)(smem + SM_B1 + tid * 16) = ((const float4*)b1)[tid];
    }

    float C[4][4][4];
    #pragma unroll
    for (int mt = 0; mt < 4; ++mt)
        #pragma unroll
        for (int nt = 0; nt < 4; ++nt)
            #pragma unroll
            for (int q = 0; q < 4; ++q) C[mt][nt][q] = 0.f;

    #pragma unroll
    for (int kc = 0; kc < 4; ++kc) {
        int buf = kc & 1;
        cp_wait0();   // B[kc] landed in smem

        // ---- convert + store A[kc] fp16 (swizzled 16B chunks) ----
        #pragma unroll
        for (int q = 0; q < 2; ++q) {
            int c = apart * 2 + q;
            union { __half2 h2[4]; uint4 u; } H;
            #pragma unroll
            for (int p = 0; p < 4; ++p) {
                H.h2[p] = __floats2half2_rn(av[buf][q * 8 + 2 * p], av[buf][q * 8 + 2 * p + 1]);
            }
            uint32_t byo = buf * 8192 + arow * 128 + ((c ^ (arow & 7)) << 4);
            *(uint4*)(smem + SA + byo) = H.u;
        }
        __syncthreads();   // A[kc] + B[kc] visible to all; prior-buf reads done (skew < 1 iter)

        // ---- launch next chunk's loads (overlap with MMA below) ----
        if (kc < 3) {
            issueB(kc + 1, buf ^ 1);
            cp_commit();
            ldgA(kc + 1, av[buf ^ 1]);
        }

        // ---- mma over 4 k16 steps on buffer `buf` ----
        uint32_t baseA  = sb + SA    + buf * 8192;
        uint32_t baseBH = sb + SB_HI + buf * 32768;
        uint32_t baseBL = sb + SB_LO + buf * 32768;
        #pragma unroll
        for (int ks = 0; ks < 4; ++ks) {
            uint32_t Ah[4][4], Bh[4][2], Bl[4][2];
            int ar = lane & 15, ac = ks * 2 + (lane >> 4);
            #pragma unroll
            for (int mt = 0; mt < 4; ++mt) {
                int r = mt * 16 + ar;
                uint32_t byo = r * 128 + ((ac ^ (r & 7)) << 4);
                ldm_x4(Ah[mt], baseA + byo);
            }
            int br = lane & 7, bc = ks * 2 + ((lane >> 3) & 1);
            #pragma unroll
            for (int nt = 0; nt < 4; ++nt) {
                int r = wid * 32 + nt * 8 + br;
                uint32_t byo = r * 128 + ((bc ^ (r & 7)) << 4);
                ldm_x2(Bh[nt], baseBH + byo);
                ldm_x2(Bl[nt], baseBL + byo);
            }
            #pragma unroll
            for (int mt = 0; mt < 4; ++mt)
                #pragma unroll
                for (int nt = 0; nt < 4; ++nt) {
                    mma_f16(C[mt][nt], Ah[mt], Bh[nt]);
                    mma_f16(C[mt][nt], Ah[mt], Bl[nt]);
                }
        }
    }
    __syncthreads();   // all frag reads done; tile smem reusable as h buffer

    // ---- epilogue: bias + relu -> smem h[64][264] ----
    float* hs  = (float*)smem;
    const float* b1s = (const float*)(smem + SM_B1);
    const float* w2s = (const float*)(smem + SM_W2);
    {
        int rq = lane >> 2, cq = (lane & 3) * 2;
        #pragma unroll
        for (int mt = 0; mt < 4; ++mt)
            #pragma unroll
            for (int nt = 0; nt < 4; ++nt) {
                int col = wid * 32 + nt * 8 + cq;
                float bx = b1s[col], by = b1s[col + 1];
                int r0 = mt * 16 + rq, r1 = r0 + 8;
                float v00 = C[mt][nt][0] + bx, v01 = C[mt][nt][1] + by;
                float v10 = C[mt][nt][2] + bx, v11 = C[mt][nt][3] + by;
                *(float2*)&hs[r0 * 264 + col] =
                    make_float2(v00 > 0.f ? v00 : 0.f, v01 > 0.f ? v01 : 0.f);
                *(float2*)&hs[r1 * 264 + col] =
                    make_float2(v10 > 0.f ? v10 : 0.f, v11 > 0.f ? v11 : 0.f);
            }
    }
    __syncthreads();

    // ---- layer-2 projection: warp per 8 rows ----
    #pragma unroll
    for (int rr = 0; rr < 8; ++rr) {
        int row = wid * 8 + rr;
        const float* hr = &hs[row * 264];
        float4 p0 = *(const float4*)&hr[lane * 8];
        float4 p1 = *(const float4*)&hr[lane * 8 + 4];
        float val = 0.f;
        #pragma unroll
        for (int o = 0; o < 8; ++o) {
            const float* wr = &w2s[o * 256 + lane * 8];
            float s = p0.x * wr[0] + p0.y * wr[1] + p0.z * wr[2] + p0.w * wr[3]
                    + p1.x * wr[4] + p1.y * wr[5] + p1.z * wr[6] + p1.w * wr[7];
            #pragma unroll
            for (int off = 16; off; off >>= 1) s += __shfl_xor_sync(FULL, s, off);
            if (lane == o) val = s;
        }
        int gr = rowBase + row;
        if (gr < NN) {
            if (lane < 4)      g_u[gr * 4 + lane]       = val;
            else if (lane < 8) g_v[gr * 4 + (lane - 4)] = val;
        }
    }
}

// ---------------- layer-2 aggregation + bias + residual + log_softmax ----------------
__global__ void k_final(const float* __restrict__ b2, float* __restrict__ out) {
    int warp = threadIdx.x >> 5, lane = threadIdx.x & 31;
    int node = blockIdx.x * 8 + warp;
    if (node >= NN) return;
    int beg = g_row_start[node], end = g_row_start[node + 1];
    int ei8 = lane >> 2, c = lane & 3;
    float acc = 0.f;
    for (int base = beg; base < end; base += 8) {
        int e = base + ei8;
        if (e < end) {
            int s = g_csr[e];
            acc += g_u[s * 4 + c];
        }
    }
    acc += __shfl_down_sync(FULL, acc, 16);
    acc += __shfl_down_sync(FULL, acc, 8);
    acc += __shfl_down_sync(FULL, acc, 4);
    float inv = (end > beg) ? 1.0f / (float)(end - beg) : 0.f;
    float val = acc * inv + b2[c] + g_v[node * 4 + c];
    float m = val;
    m = fmaxf(m, __shfl_xor_sync(FULL, m, 1));
    m = fmaxf(m, __shfl_xor_sync(FULL, m, 2));
    float ex = expf(val - m);
    float ssum = ex;
    ssum += __shfl_xor_sync(FULL, ssum, 1);
    ssum += __shfl_xor_sync(FULL, ssum, 2);
    if (lane < 4) out[node * 4 + c] = val - m - logf(ssum);
}

// ---------------- eager module load + smem opt-in (static init, outside capture) ----------------
namespace {
struct HXModuleLoad {
    HXModuleLoad() {
        cudaFuncAttributes a;
        (void)cudaFuncGetAttributes(&a, (const void*)k_hist);
        (void)cudaFuncSetAttribute((const void*)k_mma,
                                   cudaFuncAttributeMaxDynamicSharedMemorySize, SM_TOT);
    }
};
HXModuleLoad hx_module_load_;
}

// ---------------- launch ----------------
extern "C" void kernel_launch(void* const* d_in, const int* in_sizes, int n_in,
                              void* d_out, int out_size) {
    const float* x   = (const float*)d_in[0];
    const int*   ei  = (const int*)d_in[1];   // int32 edge_index: [0..E)=src, [E..2E)=dst
    const float* w1l = (const float*)d_in[2];
    const float* w1r = (const float*)d_in[3];
    const float* b1  = (const float*)d_in[4];
    const float* w2l = (const float*)d_in[5];
    const float* w2r = (const float*)d_in[6];
    const float* b2  = (const float*)d_in[7];
    float* out = (float*)d_out;

    k_wsplit<<<256, 256>>>(w1l, w1r);                 // 1: also zeroes g_cnt/g_state
    k_hist<<<(EE + 511) / 512, 512>>>(ei);            // 2
    k_scan<<<NB_SCAN, 512>>>();                       // 3: single-pass lookback scan
    k_fill<<<(EE + 255) / 256, 256>>>(ei);            // 4
    k_agg1<<<(NN + 7) / 8, 256>>>(x);                 // 5
    k_mma<<<(NN + 63) / 64, 256, SM_TOT>>>(x, b1, w2l, w2r);  // 6
    k_final<<<(NN + 7) / 8, 256>>>(b2, out);          // 7
}

// round 11
// speedup vs baseline: 1.5936x; 1.3462x over previous
#include <cuda_runtime.h>
#include <cuda_fp16.h>
#include <cstdint>

#define NN 100000
#define EE 1600000
#define FULL 0xffffffffu
#define NB_SCAN 196

// ---------------- scratch (static device globals; no allocation) ----------------
__device__ __align__(16) int   g_cnt[NN];
__device__ __align__(16) int   g_row_start[NN + 1];
__device__ __align__(16) int   g_cursor[NN];
__device__ __align__(16) int   g_csr[EE];
__device__ __align__(16) unsigned int g_state[256];   // lookback: flag(2b)|value(30b)
__device__ __align__(16) __half g_x16[12800000];      // x in fp16 [N][128]
__device__ __align__(16) __half g_aggx16[12800000];   // mean-agg in fp16 [N][128]
__device__ __align__(16) float g_u[NN * 4];
__device__ __align__(16) float g_v[NN * 4];
__device__ __align__(16) __half g_w1h[65536];         // [256 out][256 k] fp16

// ---------------- prep: W->fp16, x->fp16, scratch reset ----------------
__global__ void k_prep(const float* __restrict__ w1l, const float* __restrict__ w1r,
                       const float* __restrict__ x) {
    int idx = blockIdx.x * 256 + threadIdx.x;   // 65536 threads
    // weights
    {
        int out = idx >> 8, k = idx & 255;
        float v = (k < 128) ? w1l[out * 128 + k] : w1r[out * 128 + (k - 128)];
        g_w1h[idx] = __float2half_rn(v);
    }
    // x -> fp16 (1.6M uint4 = 12.8M halves)
    const float4* xf = (const float4*)x;
    for (int i = idx; i < 1600000; i += 65536) {
        float4 a = xf[2 * i], b = xf[2 * i + 1];
        union { __half2 h2[4]; uint4 u; } P;
        P.h2[0] = __floats2half2_rn(a.x, a.y);
        P.h2[1] = __floats2half2_rn(a.z, a.w);
        P.h2[2] = __floats2half2_rn(b.x, b.y);
        P.h2[3] = __floats2half2_rn(b.z, b.w);
        ((uint4*)g_x16)[i] = P.u;
    }
    // reset histogram + lookback state
    for (int i = idx; i < NN; i += 65536) g_cnt[i] = 0;
    if (idx < 256) g_state[idx] = 0;
}

// ---------------- histogram of in-degrees ----------------
__global__ void k_hist(const int* __restrict__ ei) {
    int e = blockIdx.x * blockDim.x + threadIdx.x;
    if (e < EE) atomicAdd(&g_cnt[ei[EE + e]], 1);
}

// ---------------- single-kernel exclusive scan (decoupled lookback) ----------------
__global__ __launch_bounds__(512) void k_scan() {
    int b = blockIdx.x, t = threadIdx.x;
    int gid = b * 512 + t;
    int v = (gid < NN) ? g_cnt[gid] : 0;

    __shared__ int s[512];
    s[t] = v;
    for (int off = 1; off < 512; off <<= 1) {
        __syncthreads();
        int add = (t >= off) ? s[t - off] : 0;
        __syncthreads();
        s[t] += add;
    }
    __syncthreads();
    int incl  = s[t];
    int total = s[511];

    __shared__ int sExcl;
    if (t == 0) {
        if (b == 0) {
            atomicExch(&g_state[0], (2u << 30) | (unsigned)total);
            sExcl = 0;
        } else {
            atomicExch(&g_state[b], (1u << 30) | (unsigned)total);
            int excl = 0, j = b - 1;
            while (true) {
                unsigned st;
                do { st = atomicAdd(&g_state[j], 0u); } while ((st >> 30) == 0u);
                excl += (int)(st & 0x3FFFFFFFu);
                if ((st >> 30) == 2u) break;
                --j;
            }
            atomicExch(&g_state[b], (2u << 30) | (unsigned)(excl + total));
            sExcl = excl;
        }
    }
    __syncthreads();
    int rs = sExcl + incl - v;   // exclusive prefix
    if (gid < NN) { g_row_start[gid] = rs; g_cursor[gid] = rs; }
    if (gid == 0) g_row_start[NN] = EE;
}

// ---------------- CSR fill ----------------
__global__ void k_fill(const int* __restrict__ ei) {
    int e = blockIdx.x * blockDim.x + threadIdx.x;
    if (e < EE) {
        int d = ei[EE + e];
        int pos = atomicAdd(&g_cursor[d], 1);
        g_csr[pos] = ei[e];
    }
}

// ---------------- layer-1 mean aggregation (fp16 gather, fp32 accum, fp16 out) ----------------
__global__ void k_agg1() {
    int warp = threadIdx.x >> 5, lane = threadIdx.x & 31;
    int node = blockIdx.x * 8 + warp;
    if (node >= NN) return;
    int beg = g_row_start[node], end = g_row_start[node + 1];
    const uint2* xv = (const uint2*)g_x16;   // 32 uint2 (8B = 4 halves) per row
    float acc0 = 0.f, acc1 = 0.f, acc2 = 0.f, acc3 = 0.f;
    int e = beg;
    for (; e + 3 < end; e += 4) {
        int s0 = g_csr[e], s1 = g_csr[e + 1], s2 = g_csr[e + 2], s3 = g_csr[e + 3];
        uint2 d0 = xv[(size_t)s0 * 32 + lane];
        uint2 d1 = xv[(size_t)s1 * 32 + lane];
        uint2 d2 = xv[(size_t)s2 * 32 + lane];
        uint2 d3 = xv[(size_t)s3 * 32 + lane];
        #pragma unroll
        for (int q = 0; q < 4; ++q) {
            uint2 d = (q == 0) ? d0 : (q == 1) ? d1 : (q == 2) ? d2 : d3;
            float2 f0 = __half22float2(*(__half2*)&d.x);
            float2 f1 = __half22float2(*(__half2*)&d.y);
            acc0 += f0.x; acc1 += f0.y; acc2 += f1.x; acc3 += f1.y;
        }
    }
    for (; e < end; ++e) {
        int s0 = g_csr[e];
        uint2 d = xv[(size_t)s0 * 32 + lane];
        float2 f0 = __half22float2(*(__half2*)&d.x);
        float2 f1 = __half22float2(*(__half2*)&d.y);
        acc0 += f0.x; acc1 += f0.y; acc2 += f1.x; acc3 += f1.y;
    }
    float inv = (end > beg) ? 1.0f / (float)(end - beg) : 0.f;
    uint2 o;
    *(__half2*)&o.x = __floats2half2_rn(acc0 * inv, acc1 * inv);
    *(__half2*)&o.y = __floats2half2_rn(acc2 * inv, acc3 * inv);
    ((uint2*)g_aggx16)[(size_t)node * 32 + lane] = o;
}

// ---------------- helpers ----------------
__device__ __forceinline__ uint32_t smem_u32(const void* p) {
    uint32_t a;
    asm("{ .reg .u64 t; cvta.to.shared.u64 t, %1; cvt.u32.u64 %0, t; }" : "=r"(a) : "l"(p));
    return a;
}
__device__ __forceinline__ void ldm_x4(uint32_t* r, uint32_t addr) {
    asm volatile("ldmatrix.sync.aligned.m8n8.x4.shared.b16 {%0,%1,%2,%3}, [%4];"
                 : "=r"(r[0]), "=r"(r[1]), "=r"(r[2]), "=r"(r[3]) : "r"(addr));
}
__device__ __forceinline__ void ldm_x2(uint32_t* r, uint32_t addr) {
    asm volatile("ldmatrix.sync.aligned.m8n8.x2.shared.b16 {%0,%1}, [%2];"
                 : "=r"(r[0]), "=r"(r[1]) : "r"(addr));
}
__device__ __forceinline__ void mma_f16(float* c, const uint32_t* a, const uint32_t* b) {
    asm volatile(
        "mma.sync.aligned.m16n8k16.row.col.f32.f16.f16.f32 "
        "{%0,%1,%2,%3}, {%4,%5,%6,%7}, {%8,%9}, {%0,%1,%2,%3};"
        : "+f"(c[0]), "+f"(c[1]), "+f"(c[2]), "+f"(c[3])
        : "r"(a[0]), "r"(a[1]), "r"(a[2]), "r"(a[3]), "r"(b[0]), "r"(b[1]));
}
__device__ __forceinline__ void cp16(uint32_t smem_addr, const void* gptr) {
    asm volatile("cp.async.cg.shared.global [%0], [%1], 16;"
                 :: "r"(smem_addr), "l"(gptr) : "memory");
}
__device__ __forceinline__ void cp16z(uint32_t smem_addr, const void* gptr, uint32_t sz) {
    asm volatile("cp.async.cg.shared.global [%0], [%1], 16, %2;"
                 :: "r"(smem_addr), "l"(gptr), "r"(sz) : "memory");
}
__device__ __forceinline__ void cp_commit() {
    asm volatile("cp.async.commit_group;" ::: "memory");
}
__device__ __forceinline__ void cp_wait0() {
    asm volatile("cp.async.wait_group 0;" ::: "memory");
}

// smem layout (bytes) — double-buffered fp16 A/B tiles
#define SA    0            // 2 x [64][64] f16 swizzled    (2 x 8 KB)
#define SB    16384        // 2 x [256][64] f16 swizzled   (2 x 32 KB)
#define SM_W2 81920        // [8][256] f32 (8 KB)
#define SM_B1 90112        // [256] f32 (1 KB)
#define SM_TOT 91136
// h buffer [64][264] f32 = 67584 B reuses [0, 67584) after mainloop

// ---------------- mma.sync fp16 GEMM + fused layer-2 projection ----------------
// Per CTA: rows rowBase..rowBase+63, all 256 output cols. 8 warps, warp tile 64x32.
// D = A16 * W16 (fp32 accum). All tiles via cp.async double buffering.
__global__ __launch_bounds__(256) void k_mma(
    const float* __restrict__ b1,
    const float* __restrict__ w2l, const float* __restrict__ w2r)
{
    extern __shared__ char smem[];
    uint32_t sb = smem_u32(smem);
    int tid = threadIdx.x, wid = tid >> 5, lane = tid & 31;
    int rowBase = blockIdx.x * 64;

    int arow = tid >> 2, apart = tid & 3;      // A: 4 threads/row, 2 x 16B chunks each
    int grow = rowBase + arow;
    uint32_t asz = (grow < NN) ? 16u : 0u;     // zero-fill OOB rows

    auto issueA = [&](int kc, int buf) {
        const __half* src = (kc < 2) ? (g_aggx16 + (size_t)grow * 128 + kc * 64)
                                     : (g_x16    + (size_t)grow * 128 + (kc - 2) * 64);
        uint32_t dst = sb + SA + buf * 8192 + arow * 128;
        #pragma unroll
        for (int q = 0; q < 2; ++q) {
            int c = apart * 2 + q;
            cp16z(dst + ((c ^ (arow & 7)) << 4), src + c * 8, asz);
        }
    };
    auto issueB = [&](int kc, int buf) {
        uint32_t dst = sb + SB + buf * 32768 + tid * 128;
        const __half* ph = g_w1h + tid * 256 + kc * 64;
        #pragma unroll
        for (int q = 0; q < 8; ++q)
            cp16(dst + ((q ^ (tid & 7)) << 4), ph + q * 8);
    };

    // ---- prologue: kick off chunk 0, stage w2/b1 ----
    issueA(0, 0);
    issueB(0, 0);
    cp_commit();
    {
        int o = tid >> 5, k = (tid & 31) * 8;
        const float* wp = (o < 4) ? (w2l + o * 256 + k) : (w2r + (o - 4) * 256 + k);
        *(float4*)(smem + SM_W2 + (size_t)(o * 256 + k) * 4)     = ((const float4*)wp)[0];
        *(float4*)(smem + SM_W2 + (size_t)(o * 256 + k + 4) * 4) = ((const float4*)wp)[1];
        if (tid < 64) *(float4*)(smem + SM_B1 + tid * 16) = ((const float4*)b1)[tid];
    }

    float C[4][4][4];
    #pragma unroll
    for (int mt = 0; mt < 4; ++mt)
        #pragma unroll
        for (int nt = 0; nt < 4; ++nt)
            #pragma unroll
            for (int q = 0; q < 4; ++q) C[mt][nt][q] = 0.f;

    #pragma unroll
    for (int kc = 0; kc < 4; ++kc) {
        int buf = kc & 1;
        cp_wait0();
        __syncthreads();   // tiles[kc] visible to all; prior-buf reads done

        if (kc < 3) {      // overlap next chunk's loads with this chunk's MMAs
            issueA(kc + 1, buf ^ 1);
            issueB(kc + 1, buf ^ 1);
            cp_commit();
        }

        uint32_t baseA = sb + SA + buf * 8192;
        uint32_t baseB = sb + SB + buf * 32768;
        #pragma unroll
        for (int ks = 0; ks < 4; ++ks) {
            uint32_t Ah[4][4], Bh[4][2];
            int ar = lane & 15, ac = ks * 2 + (lane >> 4);
            #pragma unroll
            for (int mt = 0; mt < 4; ++mt) {
                int r = mt * 16 + ar;
                ldm_x4(Ah[mt], baseA + r * 128 + ((ac ^ (r & 7)) << 4));
            }
            int br = lane & 7, bc = ks * 2 + ((lane >> 3) & 1);
            #pragma unroll
            for (int nt = 0; nt < 4; ++nt) {
                int r = wid * 32 + nt * 8 + br;
                ldm_x2(Bh[nt], baseB + r * 128 + ((bc ^ (r & 7)) << 4));
            }
            #pragma unroll
            for (int mt = 0; mt < 4; ++mt)
                #pragma unroll
                for (int nt = 0; nt < 4; ++nt)
                    mma_f16(C[mt][nt], Ah[mt], Bh[nt]);
        }
    }
    __syncthreads();   // all frag reads done; tile smem reusable as h buffer

    // ---- epilogue: bias + relu -> smem h[64][264] ----
    float* hs  = (float*)smem;
    const float* b1s = (const float*)(smem + SM_B1);
    const float* w2s = (const float*)(smem + SM_W2);
    {
        int rq = lane >> 2, cq = (lane & 3) * 2;
        #pragma unroll
        for (int mt = 0; mt < 4; ++mt)
            #pragma unroll
            for (int nt = 0; nt < 4; ++nt) {
                int col = wid * 32 + nt * 8 + cq;
                float bx = b1s[col], by = b1s[col + 1];
                int r0 = mt * 16 + rq, r1 = r0 + 8;
                float v00 = C[mt][nt][0] + bx, v01 = C[mt][nt][1] + by;
                float v10 = C[mt][nt][2] + bx, v11 = C[mt][nt][3] + by;
                *(float2*)&hs[r0 * 264 + col] =
                    make_float2(v00 > 0.f ? v00 : 0.f, v01 > 0.f ? v01 : 0.f);
                *(float2*)&hs[r1 * 264 + col] =
                    make_float2(v10 > 0.f ? v10 : 0.f, v11 > 0.f ? v11 : 0.f);
            }
    }
    __syncthreads();

    // ---- layer-2 projection: warp per 8 rows ----
    #pragma unroll
    for (int rr = 0; rr < 8; ++rr) {
        int row = wid * 8 + rr;
        const float* hr = &hs[row * 264];
        float4 p0 = *(const float4*)&hr[lane * 8];
        float4 p1 = *(const float4*)&hr[lane * 8 + 4];
        float val = 0.f;
        #pragma unroll
        for (int o = 0; o < 8; ++o) {
            const float* wr = &w2s[o * 256 + lane * 8];
            float s = p0.x * wr[0] + p0.y * wr[1] + p0.z * wr[2] + p0.w * wr[3]
                    + p1.x * wr[4] + p1.y * wr[5] + p1.z * wr[6] + p1.w * wr[7];
            #pragma unroll
            for (int off = 16; off; off >>= 1) s += __shfl_xor_sync(FULL, s, off);
            if (lane == o) val = s;
        }
        int gr = rowBase + row;
        if (gr < NN) {
            if (lane < 4)      g_u[gr * 4 + lane]       = val;
            else if (lane < 8) g_v[gr * 4 + (lane - 4)] = val;
        }
    }
}

// ---------------- layer-2 aggregation + bias + residual + log_softmax ----------------
__global__ void k_final(const float* __restrict__ b2, float* __restrict__ out) {
    int warp = threadIdx.x >> 5, lane = threadIdx.x & 31;
    int node = blockIdx.x * 8 + warp;
    if (node >= NN) return;
    int beg = g_row_start[node], end = g_row_start[node + 1];
    int ei8 = lane >> 2, c = lane & 3;
    float acc = 0.f;
    for (int base = beg; base < end; base += 8) {
        int e = base + ei8;
        if (e < end) {
            int s = g_csr[e];
            acc += g_u[s * 4 + c];
        }
    }
    acc += __shfl_down_sync(FULL, acc, 16);
    acc += __shfl_down_sync(FULL, acc, 8);
    acc += __shfl_down_sync(FULL, acc, 4);
    float inv = (end > beg) ? 1.0f / (float)(end - beg) : 0.f;
    float val = acc * inv + b2[c] + g_v[node * 4 + c];
    float m = val;
    m = fmaxf(m, __shfl_xor_sync(FULL, m, 1));
    m = fmaxf(m, __shfl_xor_sync(FULL, m, 2));
    float ex = expf(val - m);
    float ssum = ex;
    ssum += __shfl_xor_sync(FULL, ssum, 1);
    ssum += __shfl_xor_sync(FULL, ssum, 2);
    if (lane < 4) out[node * 4 + c] = val - m - logf(ssum);
}

// ---------------- eager module load + smem opt-in (static init, outside capture) ----------------
namespace {
struct HXModuleLoad {
    HXModuleLoad() {
        cudaFuncAttributes a;
        (void)cudaFuncGetAttributes(&a, (const void*)k_hist);
        (void)cudaFuncSetAttribute((const void*)k_mma,
                                   cudaFuncAttributeMaxDynamicSharedMemorySize, SM_TOT);
    }
};
HXModuleLoad hx_module_load_;
}

// ---------------- launch ----------------
extern "C" void kernel_launch(void* const* d_in, const int* in_sizes, int n_in,
                              void* d_out, int out_size) {
    const float* x   = (const float*)d_in[0];
    const int*   ei  = (const int*)d_in[1];   // int32 edge_index: [0..E)=src, [E..2E)=dst
    const float* w1l = (const float*)d_in[2];
    const float* w1r = (const float*)d_in[3];
    const float* b1  = (const float*)d_in[4];
    const float* w2l = (const float*)d_in[5];
    const float* w2r = (const float*)d_in[6];
    const float* b2  = (const float*)d_in[7];
    float* out = (float*)d_out;

    k_prep<<<256, 256>>>(w1l, w1r, x);                // 1: W/x -> fp16, zero cnt/state
    k_hist<<<(EE + 511) / 512, 512>>>(ei);            // 2
    k_scan<<<NB_SCAN, 512>>>();                       // 3: single-pass lookback scan
    k_fill<<<(EE + 255) / 256, 256>>>(ei);            // 4
    k_agg1<<<(NN + 7) / 8, 256>>>();                  // 5: fp16 gather-mean
    k_mma<<<(NN + 63) / 64, 256, SM_TOT>>>(b1, w2l, w2r);  // 6
    k_final<<<(NN + 7) / 8, 256>>>(b2, out);          // 7
}

// round 12
// speedup vs baseline: 1.7518x; 1.0993x over previous
#include <cuda_runtime.h>
#include <cuda_fp16.h>
#include <cstdint>

#define NN 100000
#define EE 1600000
#define FULL 0xffffffffu
#define NB_SCAN 196

// ---------------- scratch (static device globals; no allocation) ----------------
// NOTE: g_cnt/g_state are zero at module load and re-zeroed by k_fill each call
// (after k_scan consumes them), so k_prep's histogram always starts from zero.
__device__ __align__(16) int   g_cnt[NN];
__device__ __align__(16) int   g_row_start[NN + 1];
__device__ __align__(16) int   g_cursor[NN];
__device__ __align__(16) int   g_csr[EE];
__device__ __align__(16) unsigned int g_state[256];   // lookback: flag(2b)|value(30b)
__device__ __align__(16) __half g_x16[12800000];      // x in fp16 [N][128]
__device__ __align__(16) __half g_aggx16[12800000];   // mean-agg in fp16 [N][128]
__device__ __align__(16) float g_u[NN * 4];
__device__ __align__(16) float g_v[NN * 4];
__device__ __align__(16) __half g_w1h[65536];         // [256 out][256 k] fp16

// ---------------- prep: W->fp16, x->fp16, degree histogram ----------------
__global__ void k_prep(const float* __restrict__ w1l, const float* __restrict__ w1r,
                       const float* __restrict__ x, const int* __restrict__ ei) {
    int idx = blockIdx.x * 256 + threadIdx.x;   // 65536 threads
    // weights
    {
        int out = idx >> 8, k = idx & 255;
        float v = (k < 128) ? w1l[out * 128 + k] : w1r[out * 128 + (k - 128)];
        g_w1h[idx] = __float2half_rn(v);
    }
    // x -> fp16 (1.6M uint4 = 12.8M halves)
    const float4* xf = (const float4*)x;
    for (int i = idx; i < 1600000; i += 65536) {
        float4 a = xf[2 * i], b = xf[2 * i + 1];
        union { __half2 h2[4]; uint4 u; } P;
        P.h2[0] = __floats2half2_rn(a.x, a.y);
        P.h2[1] = __floats2half2_rn(a.z, a.w);
        P.h2[2] = __floats2half2_rn(b.x, b.y);
        P.h2[3] = __floats2half2_rn(b.z, b.w);
        ((uint4*)g_x16)[i] = P.u;
    }
    // in-degree histogram (g_cnt pre-zeroed by previous call's k_fill / module load)
    for (int e = idx; e < EE; e += 65536)
        atomicAdd(&g_cnt[ei[EE + e]], 1);
}

// ---------------- single-kernel exclusive scan (decoupled lookback) ----------------
__global__ __launch_bounds__(512) void k_scan() {
    int b = blockIdx.x, t = threadIdx.x;
    int gid = b * 512 + t;
    int v = (gid < NN) ? g_cnt[gid] : 0;

    __shared__ int s[512];
    s[t] = v;
    for (int off = 1; off < 512; off <<= 1) {
        __syncthreads();
        int add = (t >= off) ? s[t - off] : 0;
        __syncthreads();
        s[t] += add;
    }
    __syncthreads();
    int incl  = s[t];
    int total = s[511];

    __shared__ int sExcl;
    if (t == 0) {
        if (b == 0) {
            atomicExch(&g_state[0], (2u << 30) | (unsigned)total);
            sExcl = 0;
        } else {
            atomicExch(&g_state[b], (1u << 30) | (unsigned)total);
            int excl = 0, j = b - 1;
            while (true) {
                unsigned st;
                do { st = atomicAdd(&g_state[j], 0u); } while ((st >> 30) == 0u);
                excl += (int)(st & 0x3FFFFFFFu);
                if ((st >> 30) == 2u) break;
                --j;
            }
            atomicExch(&g_state[b], (2u << 30) | (unsigned)(excl + total));
            sExcl = excl;
        }
    }
    __syncthreads();
    int rs = sExcl + incl - v;   // exclusive prefix
    if (gid < NN) { g_row_start[gid] = rs; g_cursor[gid] = rs; }
    if (gid == 0) g_row_start[NN] = EE;
}

// ---------------- CSR fill + scratch reset for next call ----------------
__global__ void k_fill(const int* __restrict__ ei) {
    int e = blockIdx.x * blockDim.x + threadIdx.x;
    if (e < EE) {
        int d = ei[EE + e];
        int pos = atomicAdd(&g_cursor[d], 1);
        g_csr[pos] = ei[e];
    }
    // g_cnt/g_state are dead after k_scan: reset them here for the next call
    if (e < NN) g_cnt[e] = 0;
    if (e < 256) g_state[e] = 0;
}

// ---------------- layer-1 mean aggregation (fp16 gather, fp32 accum, fp16 out) ----------------
__global__ void k_agg1() {
    int warp = threadIdx.x >> 5, lane = threadIdx.x & 31;
    int node = blockIdx.x * 8 + warp;
    if (node >= NN) return;
    int beg = g_row_start[node], end = g_row_start[node + 1];
    const uint2* xv = (const uint2*)g_x16;   // 32 uint2 (8B = 4 halves) per row
    float acc0 = 0.f, acc1 = 0.f, acc2 = 0.f, acc3 = 0.f;
    int e = beg;
    for (; e + 3 < end; e += 4) {
        int s0 = g_csr[e], s1 = g_csr[e + 1], s2 = g_csr[e + 2], s3 = g_csr[e + 3];
        uint2 d0 = xv[(size_t)s0 * 32 + lane];
        uint2 d1 = xv[(size_t)s1 * 32 + lane];
        uint2 d2 = xv[(size_t)s2 * 32 + lane];
        uint2 d3 = xv[(size_t)s3 * 32 + lane];
        #pragma unroll
        for (int q = 0; q < 4; ++q) {
            uint2 d = (q == 0) ? d0 : (q == 1) ? d1 : (q == 2) ? d2 : d3;
            float2 f0 = __half22float2(*(__half2*)&d.x);
            float2 f1 = __half22float2(*(__half2*)&d.y);
            acc0 += f0.x; acc1 += f0.y; acc2 += f1.x; acc3 += f1.y;
        }
    }
    for (; e < end; ++e) {
        int s0 = g_csr[e];
        uint2 d = xv[(size_t)s0 * 32 + lane];
        float2 f0 = __half22float2(*(__half2*)&d.x);
        float2 f1 = __half22float2(*(__half2*)&d.y);
        acc0 += f0.x; acc1 += f0.y; acc2 += f1.x; acc3 += f1.y;
    }
    float inv = (end > beg) ? 1.0f / (float)(end - beg) : 0.f;
    uint2 o;
    *(__half2*)&o.x = __floats2half2_rn(acc0 * inv, acc1 * inv);
    *(__half2*)&o.y = __floats2half2_rn(acc2 * inv, acc3 * inv);
    ((uint2*)g_aggx16)[(size_t)node * 32 + lane] = o;
}

// ---------------- helpers ----------------
__device__ __forceinline__ uint32_t smem_u32(const void* p) {
    uint32_t a;
    asm("{ .reg .u64 t; cvta.to.shared.u64 t, %1; cvt.u32.u64 %0, t; }" : "=r"(a) : "l"(p));
    return a;
}
__device__ __forceinline__ void ldm_x4(uint32_t* r, uint32_t addr) {
    asm volatile("ldmatrix.sync.aligned.m8n8.x4.shared.b16 {%0,%1,%2,%3}, [%4];"
                 : "=r"(r[0]), "=r"(r[1]), "=r"(r[2]), "=r"(r[3]) : "r"(addr));
}
__device__ __forceinline__ void ldm_x2(uint32_t* r, uint32_t addr) {
    asm volatile("ldmatrix.sync.aligned.m8n8.x2.shared.b16 {%0,%1}, [%2];"
                 : "=r"(r[0]), "=r"(r[1]) : "r"(addr));
}
__device__ __forceinline__ void mma_f16(float* c, const uint32_t* a, const uint32_t* b) {
    asm volatile(
        "mma.sync.aligned.m16n8k16.row.col.f32.f16.f16.f32 "
        "{%0,%1,%2,%3}, {%4,%5,%6,%7}, {%8,%9}, {%0,%1,%2,%3};"
        : "+f"(c[0]), "+f"(c[1]), "+f"(c[2]), "+f"(c[3])
        : "r"(a[0]), "r"(a[1]), "r"(a[2]), "r"(a[3]), "r"(b[0]), "r"(b[1]));
}
__device__ __forceinline__ void cp16(uint32_t smem_addr, const void* gptr) {
    asm volatile("cp.async.cg.shared.global [%0], [%1], 16;"
                 :: "r"(smem_addr), "l"(gptr) : "memory");
}
__device__ __forceinline__ void cp16z(uint32_t smem_addr, const void* gptr, uint32_t sz) {
    asm volatile("cp.async.cg.shared.global [%0], [%1], 16, %2;"
                 :: "r"(smem_addr), "l"(gptr), "r"(sz) : "memory");
}
__device__ __forceinline__ void cp_commit() {
    asm volatile("cp.async.commit_group;" ::: "memory");
}
__device__ __forceinline__ void cp_wait0() {
    asm volatile("cp.async.wait_group 0;" ::: "memory");
}

// smem layout (bytes) — double-buffered fp16 A/B tiles
#define SA    0            // 2 x [64][64] f16 swizzled    (2 x 8 KB)
#define SB    16384        // 2 x [256][64] f16 swizzled   (2 x 32 KB)
#define SM_W2 81920        // [8][256] f32 (8 KB)
#define SM_B1 90112        // [256] f32 (1 KB)
#define SM_TOT 91136
// h buffer [64][264] f32 = 67584 B reuses [0, 67584) after mainloop

// ---------------- mma.sync fp16 GEMM + fused layer-2 projection ----------------
// Per CTA: rows rowBase..rowBase+63, all 256 output cols. 8 warps, warp tile 64x32.
// D = A16 * W16 (fp32 accum). All tiles via cp.async double buffering. 2 CTAs/SM.
__global__ __launch_bounds__(256, 2) void k_mma(
    const float* __restrict__ b1,
    const float* __restrict__ w2l, const float* __restrict__ w2r)
{
    extern __shared__ char smem[];
    uint32_t sb = smem_u32(smem);
    int tid = threadIdx.x, wid = tid >> 5, lane = tid & 31;
    int rowBase = blockIdx.x * 64;

    int arow = tid >> 2, apart = tid & 3;      // A: 4 threads/row, 2 x 16B chunks each
    int grow = rowBase + arow;
    uint32_t asz = (grow < NN) ? 16u : 0u;     // zero-fill OOB rows

    auto issueA = [&](int kc, int buf) {
        const __half* src = (kc < 2) ? (g_aggx16 + (size_t)grow * 128 + kc * 64)
                                     : (g_x16    + (size_t)grow * 128 + (kc - 2) * 64);
        uint32_t dst = sb + SA + buf * 8192 + arow * 128;
        #pragma unroll
        for (int q = 0; q < 2; ++q) {
            int c = apart * 2 + q;
            cp16z(dst + ((c ^ (arow & 7)) << 4), src + c * 8, asz);
        }
    };
    auto issueB = [&](int kc, int buf) {
        uint32_t dst = sb + SB + buf * 32768 + tid * 128;
        const __half* ph = g_w1h + tid * 256 + kc * 64;
        #pragma unroll
        for (int q = 0; q < 8; ++q)
            cp16(dst + ((q ^ (tid & 7)) << 4), ph + q * 8);
    };

    // ---- prologue: kick off chunk 0, stage w2/b1 ----
    issueA(0, 0);
    issueB(0, 0);
    cp_commit();
    {
        int o = tid >> 5, k = (tid & 31) * 8;
        const float* wp = (o < 4) ? (w2l + o * 256 + k) : (w2r + (o - 4) * 256 + k);
        *(float4*)(smem + SM_W2 + (size_t)(o * 256 + k) * 4)     = ((const float4*)wp)[0];
        *(float4*)(smem + SM_W2 + (size_t)(o * 256 + k + 4) * 4) = ((const float4*)wp)[1];
        if (tid < 64) *(float4*)(smem + SM_B1 + tid * 16) = ((const float4*)b1)[tid];
    }

    float C[4][4][4];
    #pragma unroll
    for (int mt = 0; mt < 4; ++mt)
        #pragma unroll
        for (int nt = 0; nt < 4; ++nt)
            #pragma unroll
            for (int q = 0; q < 4; ++q) C[mt][nt][q] = 0.f;

    #pragma unroll
    for (int kc = 0; kc < 4; ++kc) {
        int buf = kc & 1;
        cp_wait0();
        __syncthreads();   // tiles[kc] visible to all; prior-buf reads done

        if (kc < 3) {      // overlap next chunk's loads with this chunk's MMAs
            issueA(kc + 1, buf ^ 1);
            issueB(kc + 1, buf ^ 1);
            cp_commit();
        }

        uint32_t baseA = sb + SA + buf * 8192;
        uint32_t baseB = sb + SB + buf * 32768;
        #pragma unroll
        for (int ks = 0; ks < 4; ++ks) {
            uint32_t Ah[4][4], Bh[4][2];
            int ar = lane & 15, ac = ks * 2 + (lane >> 4);
            #pragma unroll
            for (int mt = 0; mt < 4; ++mt) {
                int r = mt * 16 + ar;
                ldm_x4(Ah[mt], baseA + r * 128 + ((ac ^ (r & 7)) << 4));
            }
            int br = lane & 7, bc = ks * 2 + ((lane >> 3) & 1);
            #pragma unroll
            for (int nt = 0; nt < 4; ++nt) {
                int r = wid * 32 + nt * 8 + br;
                ldm_x2(Bh[nt], baseB + r * 128 + ((bc ^ (r & 7)) << 4));
            }
            #pragma unroll
            for (int mt = 0; mt < 4; ++mt)
                #pragma unroll
                for (int nt = 0; nt < 4; ++nt)
                    mma_f16(C[mt][nt], Ah[mt], Bh[nt]);
        }
    }
    __syncthreads();   // all frag reads done; tile smem reusable as h buffer

    // ---- epilogue: bias + relu -> smem h[64][264] ----
    float* hs  = (float*)smem;
    const float* b1s = (const float*)(smem + SM_B1);
    const float* w2s = (const float*)(smem + SM_W2);
    {
        int rq = lane >> 2, cq = (lane & 3) * 2;
        #pragma unroll
        for (int mt = 0; mt < 4; ++mt)
            #pragma unroll
            for (int nt = 0; nt < 4; ++nt) {
                int col = wid * 32 + nt * 8 + cq;
                float bx = b1s[col], by = b1s[col + 1];
                int r0 = mt * 16 + rq, r1 = r0 + 8;
                float v00 = C[mt][nt][0] + bx, v01 = C[mt][nt][1] + by;
                float v10 = C[mt][nt][2] + bx, v11 = C[mt][nt][3] + by;
                *(float2*)&hs[r0 * 264 + col] =
                    make_float2(v00 > 0.f ? v00 : 0.f, v01 > 0.f ? v01 : 0.f);
                *(float2*)&hs[r1 * 264 + col] =
                    make_float2(v10 > 0.f ? v10 : 0.f, v11 > 0.f ? v11 : 0.f);
            }
    }
    __syncthreads();

    // ---- layer-2 projection: warp per 8 rows ----
    #pragma unroll
    for (int rr = 0; rr < 8; ++rr) {
        int row = wid * 8 + rr;
        const float* hr = &hs[row * 264];
        float4 p0 = *(const float4*)&hr[lane * 8];
        float4 p1 = *(const float4*)&hr[lane * 8 + 4];
        float val = 0.f;
        #pragma unroll
        for (int o = 0; o < 8; ++o) {
            const float* wr = &w2s[o * 256 + lane * 8];
            float s = p0.x * wr[0] + p0.y * wr[1] + p0.z * wr[2] + p0.w * wr[3]
                    + p1.x * wr[4] + p1.y * wr[5] + p1.z * wr[6] + p1.w * wr[7];
            #pragma unroll
            for (int off = 16; off; off >>= 1) s += __shfl_xor_sync(FULL, s, off);
            if (lane == o) val = s;
        }
        int gr = rowBase + row;
        if (gr < NN) {
            if (lane < 4)      g_u[gr * 4 + lane]       = val;
            else if (lane < 8) g_v[gr * 4 + (lane - 4)] = val;
        }
    }
}

// ---------------- layer-2 aggregation + bias + residual + log_softmax ----------------
__global__ void k_final(const float* __restrict__ b2, float* __restrict__ out) {
    int warp = threadIdx.x >> 5, lane = threadIdx.x & 31;
    int node = blockIdx.x * 8 + warp;
    if (node >= NN) return;
    int beg = g_row_start[node], end = g_row_start[node + 1];
    int ei8 = lane >> 2, c = lane & 3;
    float acc = 0.f;
    for (int base = beg; base < end; base += 8) {
        int e = base + ei8;
        if (e < end) {
            int s = g_csr[e];
            acc += g_u[s * 4 + c];
        }
    }
    acc += __shfl_down_sync(FULL, acc, 16);
    acc += __shfl_down_sync(FULL, acc, 8);
    acc += __shfl_down_sync(FULL, acc, 4);
    float inv = (end > beg) ? 1.0f / (float)(end - beg) : 0.f;
    float val = acc * inv + b2[c] + g_v[node * 4 + c];
    float m = val;
    m = fmaxf(m, __shfl_xor_sync(FULL, m, 1));
    m = fmaxf(m, __shfl_xor_sync(FULL, m, 2));
    float ex = expf(val - m);
    float ssum = ex;
    ssum += __shfl_xor_sync(FULL, ssum, 1);
    ssum += __shfl_xor_sync(FULL, ssum, 2);
    if (lane < 4) out[node * 4 + c] = val - m - logf(ssum);
}

// ---------------- eager module load + smem opt-in (static init, outside capture) ----------------
namespace {
struct HXModuleLoad {
    HXModuleLoad() {
        cudaFuncAttributes a;
        (void)cudaFuncGetAttributes(&a, (const void*)k_prep);
        (void)cudaFuncSetAttribute((const void*)k_mma,
                                   cudaFuncAttributeMaxDynamicSharedMemorySize, SM_TOT);
    }
};
HXModuleLoad hx_module_load_;
}

// ---------------- launch ----------------
extern "C" void kernel_launch(void* const* d_in, const int* in_sizes, int n_in,
                              void* d_out, int out_size) {
    const float* x   = (const float*)d_in[0];
    const int*   ei  = (const int*)d_in[1];   // int32 edge_index: [0..E)=src, [E..2E)=dst
    const float* w1l = (const float*)d_in[2];
    const float* w1r = (const float*)d_in[3];
    const float* b1  = (const float*)d_in[4];
    const float* w2l = (const float*)d_in[5];
    const float* w2r = (const float*)d_in[6];
    const float* b2  = (const float*)d_in[7];
    float* out = (float*)d_out;

    k_prep<<<256, 256>>>(w1l, w1r, x, ei);            // 1: W/x -> fp16 + histogram
    k_scan<<<NB_SCAN, 512>>>();                       // 2: single-pass lookback scan
    k_fill<<<(EE + 255) / 256, 256>>>(ei);            // 3: CSR fill + reset cnt/state
    k_agg1<<<(NN + 7) / 8, 256>>>();                  // 4: fp16 gather-mean
    k_mma<<<(NN + 63) / 64, 256, SM_TOT>>>(b1, w2l, w2r);  // 5
    k_final<<<(NN + 7) / 8, 256>>>(b2, out);          // 6
}

// round 13
// speedup vs baseline: 1.7670x; 1.0086x over previous
#include <cuda_runtime.h>
#include <cuda_fp16.h>
#include <cstdint>

#define NN 100000
#define EE 1600000
#define FULL 0xffffffffu
#define NB_SCAN 196

// ---------------- scratch (static device globals; no allocation) ----------------
// NOTE: g_cnt/g_state are zero at module load and re-zeroed by k_fill each call
// (after k_scan consumes them), so k_prep's histogram always starts from zero.
__device__ __align__(16) int   g_cnt[NN];
__device__ __align__(16) int   g_row_start[NN + 1];
__device__ __align__(16) int   g_cursor[NN];
__device__ __align__(16) int   g_csr[EE];
__device__ __align__(16) unsigned int g_state[256];   // lookback: flag(2b)|value(30b)
__device__ __align__(16) __half g_x16[12800000];      // x in fp16 [N][128]
__device__ __align__(16) __half g_aggx16[12800000];   // mean-agg in fp16 [N][128]
__device__ __align__(16) float g_u[NN * 4];
__device__ __align__(16) float g_v[NN * 4];
__device__ __align__(16) __half g_w1h[65536];         // [256 out][256 k] fp16

// ---------------- prep: W->fp16, x->fp16, degree histogram ----------------
__global__ void k_prep(const float* __restrict__ w1l, const float* __restrict__ w1r,
                       const float* __restrict__ x, const int* __restrict__ ei) {
    int idx = blockIdx.x * 256 + threadIdx.x;   // 131072 threads
    // weights (first 65536 threads)
    if (idx < 65536) {
        int out = idx >> 8, k = idx & 255;
        float v = (k < 128) ? w1l[out * 128 + k] : w1r[out * 128 + (k - 128)];
        g_w1h[idx] = __float2half_rn(v);
    }
    // x -> fp16 (1.6M uint4 = 12.8M halves)
    const float4* xf = (const float4*)x;
    for (int i = idx; i < 1600000; i += 131072) {
        float4 a = xf[2 * i], b = xf[2 * i + 1];
        union { __half2 h2[4]; uint4 u; } P;
        P.h2[0] = __floats2half2_rn(a.x, a.y);
        P.h2[1] = __floats2half2_rn(a.z, a.w);
        P.h2[2] = __floats2half2_rn(b.x, b.y);
        P.h2[3] = __floats2half2_rn(b.z, b.w);
        ((uint4*)g_x16)[i] = P.u;
    }
    // in-degree histogram (g_cnt pre-zeroed by previous call's k_fill / module load)
    for (int e = idx; e < EE; e += 131072)
        atomicAdd(&g_cnt[ei[EE + e]], 1);
}

// ---------------- single-kernel exclusive scan (decoupled lookback) ----------------
__global__ __launch_bounds__(512) void k_scan() {
    int b = blockIdx.x, t = threadIdx.x;
    int gid = b * 512 + t;
    int v = (gid < NN) ? g_cnt[gid] : 0;

    __shared__ int s[512];
    s[t] = v;
    for (int off = 1; off < 512; off <<= 1) {
        __syncthreads();
        int add = (t >= off) ? s[t - off] : 0;
        __syncthreads();
        s[t] += add;
    }
    __syncthreads();
    int incl  = s[t];
    int total = s[511];

    __shared__ int sExcl;
    if (t == 0) {
        if (b == 0) {
            atomicExch(&g_state[0], (2u << 30) | (unsigned)total);
            sExcl = 0;
        } else {
            atomicExch(&g_state[b], (1u << 30) | (unsigned)total);
            int excl = 0, j = b - 1;
            while (true) {
                unsigned st;
                do { st = atomicAdd(&g_state[j], 0u); } while ((st >> 30) == 0u);
                excl += (int)(st & 0x3FFFFFFFu);
                if ((st >> 30) == 2u) break;
                --j;
            }
            atomicExch(&g_state[b], (2u << 30) | (unsigned)(excl + total));
            sExcl = excl;
        }
    }
    __syncthreads();
    int rs = sExcl + incl - v;   // exclusive prefix
    if (gid < NN) { g_row_start[gid] = rs; g_cursor[gid] = rs; }
    if (gid == 0) g_row_start[NN] = EE;
}

// ---------------- CSR fill + scratch reset for next call ----------------
__global__ void k_fill(const int* __restrict__ ei) {
    int e = blockIdx.x * blockDim.x + threadIdx.x;
    if (e < EE) {
        int d = ei[EE + e];
        int pos = atomicAdd(&g_cursor[d], 1);
        g_csr[pos] = ei[e];
    }
    // g_cnt/g_state are dead after k_scan: reset them here for the next call
    if (e < NN) g_cnt[e] = 0;
    if (e < 256) g_state[e] = 0;
}

// ---------------- layer-1 mean aggregation (fp16 gather, HADD2 pair, fp32 accum) ----------------
__global__ void k_agg1() {
    int warp = threadIdx.x >> 5, lane = threadIdx.x & 31;
    int node = blockIdx.x * 8 + warp;
    if (node >= NN) return;
    int beg = g_row_start[node], end = g_row_start[node + 1];
    const uint2* xv = (const uint2*)g_x16;   // 32 uint2 (8B = 4 halves) per row
    float acc0 = 0.f, acc1 = 0.f, acc2 = 0.f, acc3 = 0.f;
    int e = beg;
    for (; e + 3 < end; e += 4) {
        int s0 = g_csr[e], s1 = g_csr[e + 1], s2 = g_csr[e + 2], s3 = g_csr[e + 3];
        uint2 d0 = xv[(size_t)s0 * 32 + lane];
        uint2 d1 = xv[(size_t)s1 * 32 + lane];
        uint2 d2 = xv[(size_t)s2 * 32 + lane];
        uint2 d3 = xv[(size_t)s3 * 32 + lane];
        // pairwise fp16 add (one extra rounding, ~2^-11), then fp32 accumulate
        __half2 p0 = __hadd2(*(__half2*)&d0.x, *(__half2*)&d1.x);
        __half2 p1 = __hadd2(*(__half2*)&d0.y, *(__half2*)&d1.y);
        __half2 p2 = __hadd2(*(__half2*)&d2.x, *(__half2*)&d3.x);
        __half2 p3 = __hadd2(*(__half2*)&d2.y, *(__half2*)&d3.y);
        float2 f0 = __half22float2(p0);
        float2 f1 = __half22float2(p1);
        float2 f2 = __half22float2(p2);
        float2 f3 = __half22float2(p3);
        acc0 += f0.x + f2.x;
        acc1 += f0.y + f2.y;
        acc2 += f1.x + f3.x;
        acc3 += f1.y + f3.y;
    }
    for (; e < end; ++e) {
        int s0 = g_csr[e];
        uint2 d = xv[(size_t)s0 * 32 + lane];
        float2 f0 = __half22float2(*(__half2*)&d.x);
        float2 f1 = __half22float2(*(__half2*)&d.y);
        acc0 += f0.x; acc1 += f0.y; acc2 += f1.x; acc3 += f1.y;
    }
    float inv = (end > beg) ? 1.0f / (float)(end - beg) : 0.f;
    uint2 o;
    *(__half2*)&o.x = __floats2half2_rn(acc0 * inv, acc1 * inv);
    *(__half2*)&o.y = __floats2half2_rn(acc2 * inv, acc3 * inv);
    ((uint2*)g_aggx16)[(size_t)node * 32 + lane] = o;
}

// ---------------- helpers ----------------
__device__ __forceinline__ uint32_t smem_u32(const void* p) {
    uint32_t a;
    asm("{ .reg .u64 t; cvta.to.shared.u64 t, %1; cvt.u32.u64 %0, t; }" : "=r"(a) : "l"(p));
    return a;
}
__device__ __forceinline__ void ldm_x4(uint32_t* r, uint32_t addr) {
    asm volatile("ldmatrix.sync.aligned.m8n8.x4.shared.b16 {%0,%1,%2,%3}, [%4];"
                 : "=r"(r[0]), "=r"(r[1]), "=r"(r[2]), "=r"(r[3]) : "r"(addr));
}
__device__ __forceinline__ void ldm_x2(uint32_t* r, uint32_t addr) {
    asm volatile("ldmatrix.sync.aligned.m8n8.x2.shared.b16 {%0,%1}, [%2];"
                 : "=r"(r[0]), "=r"(r[1]) : "r"(addr));
}
__device__ __forceinline__ void mma_f16(float* c, const uint32_t* a, const uint32_t* b) {
    asm volatile(
        "mma.sync.aligned.m16n8k16.row.col.f32.f16.f16.f32 "
        "{%0,%1,%2,%3}, {%4,%5,%6,%7}, {%8,%9}, {%0,%1,%2,%3};"
        : "+f"(c[0]), "+f"(c[1]), "+f"(c[2]), "+f"(c[3])
        : "r"(a[0]), "r"(a[1]), "r"(a[2]), "r"(a[3]), "r"(b[0]), "r"(b[1]));
}
__device__ __forceinline__ void cp16(uint32_t smem_addr, const void* gptr) {
    asm volatile("cp.async.cg.shared.global [%0], [%1], 16;"
                 :: "r"(smem_addr), "l"(gptr) : "memory");
}
__device__ __forceinline__ void cp16z(uint32_t smem_addr, const void* gptr, uint32_t sz) {
    asm volatile("cp.async.cg.shared.global [%0], [%1], 16, %2;"
                 :: "r"(smem_addr), "l"(gptr), "r"(sz) : "memory");
}
__device__ __forceinline__ void cp_commit() {
    asm volatile("cp.async.commit_group;" ::: "memory");
}
__device__ __forceinline__ void cp_wait0() {
    asm volatile("cp.async.wait_group 0;" ::: "memory");
}

// smem layout (bytes) — double-buffered fp16 A/B tiles
#define SA    0            // 2 x [64][64] f16 swizzled    (2 x 8 KB)
#define SB    16384        // 2 x [256][64] f16 swizzled   (2 x 32 KB)
#define SM_W2 81920        // [8][256] f32 (8 KB)
#define SM_B1 90112        // [256] f32 (1 KB)
#define SM_TOT 91136
// h buffer [64][264] f32 = 67584 B reuses [0, 67584) after mainloop

// ---------------- mma.sync fp16 GEMM + fused layer-2 projection ----------------
// Per CTA: rows rowBase..rowBase+63, all 256 output cols. 8 warps, warp tile 64x32.
// D = A16 * W16 (fp32 accum). All tiles via cp.async double buffering. 2 CTAs/SM.
__global__ __launch_bounds__(256, 2) void k_mma(
    const float* __restrict__ b1,
    const float* __restrict__ w2l, const float* __restrict__ w2r)
{
    extern __shared__ char smem[];
    uint32_t sb = smem_u32(smem);
    int tid = threadIdx.x, wid = tid >> 5, lane = tid & 31;
    int rowBase = blockIdx.x * 64;

    int arow = tid >> 2, apart = tid & 3;      // A: 4 threads/row, 2 x 16B chunks each
    int grow = rowBase + arow;
    uint32_t asz = (grow < NN) ? 16u : 0u;     // zero-fill OOB rows

    auto issueA = [&](int kc, int buf) {
        const __half* src = (kc < 2) ? (g_aggx16 + (size_t)grow * 128 + kc * 64)
                                     : (g_x16    + (size_t)grow * 128 + (kc - 2) * 64);
        uint32_t dst = sb + SA + buf * 8192 + arow * 128;
        #pragma unroll
        for (int q = 0; q < 2; ++q) {
            int c = apart * 2 + q;
            cp16z(dst + ((c ^ (arow & 7)) << 4), src + c * 8, asz);
        }
    };
    auto issueB = [&](int kc, int buf) {
        uint32_t dst = sb + SB + buf * 32768 + tid * 128;
        const __half* ph = g_w1h + tid * 256 + kc * 64;
        #pragma unroll
        for (int q = 0; q < 8; ++q)
            cp16(dst + ((q ^ (tid & 7)) << 4), ph + q * 8);
    };

    // ---- prologue: kick off chunk 0, stage w2/b1 ----
    issueA(0, 0);
    issueB(0, 0);
    cp_commit();
    {
        int o = tid >> 5, k = (tid & 31) * 8;
        const float* wp = (o < 4) ? (w2l + o * 256 + k) : (w2r + (o - 4) * 256 + k);
        *(float4*)(smem + SM_W2 + (size_t)(o * 256 + k) * 4)     = ((const float4*)wp)[0];
        *(float4*)(smem + SM_W2 + (size_t)(o * 256 + k + 4) * 4) = ((const float4*)wp)[1];
        if (tid < 64) *(float4*)(smem + SM_B1 + tid * 16) = ((const float4*)b1)[tid];
    }

    float C[4][4][4];
    #pragma unroll
    for (int mt = 0; mt < 4; ++mt)
        #pragma unroll
        for (int nt = 0; nt < 4; ++nt)
            #pragma unroll
            for (int q = 0; q < 4; ++q) C[mt][nt][q] = 0.f;

    #pragma unroll
    for (int kc = 0; kc < 4; ++kc) {
        int buf = kc & 1;
        cp_wait0();
        __syncthreads();   // tiles[kc] visible to all; prior-buf reads done

        if (kc < 3) {      // overlap next chunk's loads with this chunk's MMAs
            issueA(kc + 1, buf ^ 1);
            issueB(kc + 1, buf ^ 1);
            cp_commit();
        }

        uint32_t baseA = sb + SA + buf * 8192;
        uint32_t baseB = sb + SB + buf * 32768;
        #pragma unroll
        for (int ks = 0; ks < 4; ++ks) {
            uint32_t Ah[4][4], Bh[4][2];
            int ar = lane & 15, ac = ks * 2 + (lane >> 4);
            #pragma unroll
            for (int mt = 0; mt < 4; ++mt) {
                int r = mt * 16 + ar;
                ldm_x4(Ah[mt], baseA + r * 128 + ((ac ^ (r & 7)) << 4));
            }
            int br = lane & 7, bc = ks * 2 + ((lane >> 3) & 1);
            #pragma unroll
            for (int nt = 0; nt < 4; ++nt) {
                int r = wid * 32 + nt * 8 + br;
                ldm_x2(Bh[nt], baseB + r * 128 + ((bc ^ (r & 7)) << 4));
            }
            #pragma unroll
            for (int mt = 0; mt < 4; ++mt)
                #pragma unroll
                for (int nt = 0; nt < 4; ++nt)
                    mma_f16(C[mt][nt], Ah[mt], Bh[nt]);
        }
    }
    __syncthreads();   // all frag reads done; tile smem reusable as h buffer

    // ---- epilogue: bias + relu -> smem h[64][264] ----
    float* hs  = (float*)smem;
    const float* b1s = (const float*)(smem + SM_B1);
    const float* w2s = (const float*)(smem + SM_W2);
    {
        int rq = lane >> 2, cq = (lane & 3) * 2;
        #pragma unroll
        for (int mt = 0; mt < 4; ++mt)
            #pragma unroll
            for (int nt = 0; nt < 4; ++nt) {
                int col = wid * 32 + nt * 8 + cq;
                float bx = b1s[col], by = b1s[col + 1];
                int r0 = mt * 16 + rq, r1 = r0 + 8;
                float v00 = C[mt][nt][0] + bx, v01 = C[mt][nt][1] + by;
                float v10 = C[mt][nt][2] + bx, v11 = C[mt][nt][3] + by;
                *(float2*)&hs[r0 * 264 + col] =
                    make_float2(v00 > 0.f ? v00 : 0.f, v01 > 0.f ? v01 : 0.f);
                *(float2*)&hs[r1 * 264 + col] =
                    make_float2(v10 > 0.f ? v10 : 0.f, v11 > 0.f ? v11 : 0.f);
            }
    }
    __syncthreads();

    // ---- layer-2 projection: warp per 8 rows ----
    #pragma unroll
    for (int rr = 0; rr < 8; ++rr) {
        int row = wid * 8 + rr;
        const float* hr = &hs[row * 264];
        float4 p0 = *(const float4*)&hr[lane * 8];
        float4 p1 = *(const float4*)&hr[lane * 8 + 4];
        float val = 0.f;
        #pragma unroll
        for (int o = 0; o < 8; ++o) {
            const float* wr = &w2s[o * 256 + lane * 8];
            float s = p0.x * wr[0] + p0.y * wr[1] + p0.z * wr[2] + p0.w * wr[3]
                    + p1.x * wr[4] + p1.y * wr[5] + p1.z * wr[6] + p1.w * wr[7];
            #pragma unroll
            for (int off = 16; off; off >>= 1) s += __shfl_xor_sync(FULL, s, off);
            if (lane == o) val = s;
        }
        int gr = rowBase + row;
        if (gr < NN) {
            if (lane < 4)      g_u[gr * 4 + lane]       = val;
            else if (lane < 8) g_v[gr * 4 + (lane - 4)] = val;
        }
    }
}

// ---------------- layer-2 aggregation + bias + residual + log_softmax ----------------
__global__ void k_final(const float* __restrict__ b2, float* __restrict__ out) {
    int warp = threadIdx.x >> 5, lane = threadIdx.x & 31;
    int node = blockIdx.x * 8 + warp;
    if (node >= NN) return;
    int beg = g_row_start[node], end = g_row_start[node + 1];
    int ei8 = lane >> 2, c = lane & 3;
    float acc = 0.f;
    for (int base = beg; base < end; base += 8) {
        int e = base + ei8;
        if (e < end) {
            int s = g_csr[e];
            acc += g_u[s * 4 + c];
        }
    }
    acc += __shfl_down_sync(FULL, acc, 16);
    acc += __shfl_down_sync(FULL, acc, 8);
    acc += __shfl_down_sync(FULL, acc, 4);
    float inv = (end > beg) ? 1.0f / (float)(end - beg) : 0.f;
    float val = acc * inv + b2[c] + g_v[node * 4 + c];
    float m = val;
    m = fmaxf(m, __shfl_xor_sync(FULL, m, 1));
    m = fmaxf(m, __shfl_xor_sync(FULL, m, 2));
    float ex = expf(val - m);
    float ssum = ex;
    ssum += __shfl_xor_sync(FULL, ssum, 1);
    ssum += __shfl_xor_sync(FULL, ssum, 2);
    if (lane < 4) out[node * 4 + c] = val - m - logf(ssum);
}

// ---------------- eager module load + smem opt-in (static init, outside capture) ----------------
namespace {
struct HXModuleLoad {
    HXModuleLoad() {
        cudaFuncAttributes a;
        (void)cudaFuncGetAttributes(&a, (const void*)k_prep);
        (void)cudaFuncSetAttribute((const void*)k_mma,
                                   cudaFuncAttributeMaxDynamicSharedMemorySize, SM_TOT);
    }
};
HXModuleLoad hx_module_load_;
}

// ---------------- launch ----------------
extern "C" void kernel_launch(void* const* d_in, const int* in_sizes, int n_in,
                              void* d_out, int out_size) {
    const float* x   = (const float*)d_in[0];
    const int*   ei  = (const int*)d_in[1];   // int32 edge_index: [0..E)=src, [E..2E)=dst
    const float* w1l = (const float*)d_in[2];
    const float* w1r = (const float*)d_in[3];
    const float* b1  = (const float*)d_in[4];
    const float* w2l = (const float*)d_in[5];
    const float* w2r = (const float*)d_in[6];
    const float* b2  = (const float*)d_in[7];
    float* out = (float*)d_out;

    k_prep<<<512, 256>>>(w1l, w1r, x, ei);            // 1: W/x -> fp16 + histogram
    k_scan<<<NB_SCAN, 512>>>();                       // 2: single-pass lookback scan
    k_fill<<<(EE + 255) / 256, 256>>>(ei);            // 3: CSR fill + reset cnt/state
    k_agg1<<<(NN + 7) / 8, 256>>>();                  // 4: fp16 gather-mean (HADD2 pairs)
    k_mma<<<(NN + 63) / 64, 256, SM_TOT>>>(b1, w2l, w2r);  // 5
    k_final<<<(NN + 7) / 8, 256>>>(b2, out);          // 6
}

// round 14
// speedup vs baseline: 1.7999x; 1.0186x over previous
#include <cuda_runtime.h>
#include <cuda_fp16.h>
#include <cstdint>

#define NN 100000
#define EE 1600000
#define FULL 0xffffffffu
#define NB_SCAN 196

// ---------------- scratch (static device globals; no allocation) ----------------
// NOTE: g_cnt/g_state are zero at module load and re-zeroed by k_fill each call
// (after k_scan consumes them), so k_prep's histogram always starts from zero.
__device__ __align__(16) int   g_cnt[NN];
__device__ __align__(16) int   g_row_start[NN + 1];
__device__ __align__(16) int   g_cursor[NN];
__device__ __align__(16) int   g_csr[EE];
__device__ __align__(16) unsigned int g_state[256];   // lookback: flag(2b)|value(30b)
__device__ __align__(16) __half g_x16[12800000];      // x in fp16 [N][128]
__device__ __align__(16) __half g_aggx16[12800000];   // mean-agg in fp16 [N][128]
__device__ __align__(16) float g_u[NN * 4];
__device__ __align__(16) float g_v[NN * 4];
__device__ __align__(16) __half g_w1h[65536];         // [256 out][256 k] fp16

// ---------------- prep: W->fp16, x->fp16, degree histogram ----------------
__global__ void k_prep(const float* __restrict__ w1l, const float* __restrict__ w1r,
                       const float* __restrict__ x, const int* __restrict__ ei) {
    int idx = blockIdx.x * 256 + threadIdx.x;   // 131072 threads
    // weights (first 65536 threads)
    if (idx < 65536) {
        int out = idx >> 8, k = idx & 255;
        float v = (k < 128) ? w1l[out * 128 + k] : w1r[out * 128 + (k - 128)];
        g_w1h[idx] = __float2half_rn(v);
    }
    // x -> fp16 (1.6M uint4 = 12.8M halves)
    const float4* xf = (const float4*)x;
    for (int i = idx; i < 1600000; i += 131072) {
        float4 a = xf[2 * i], b = xf[2 * i + 1];
        union { __half2 h2[4]; uint4 u; } P;
        P.h2[0] = __floats2half2_rn(a.x, a.y);
        P.h2[1] = __floats2half2_rn(a.z, a.w);
        P.h2[2] = __floats2half2_rn(b.x, b.y);
        P.h2[3] = __floats2half2_rn(b.z, b.w);
        ((uint4*)g_x16)[i] = P.u;
    }
    // in-degree histogram (g_cnt pre-zeroed by previous call's k_fill / module load)
    for (int e = idx; e < EE; e += 131072)
        atomicAdd(&g_cnt[ei[EE + e]], 1);
}

// ---------------- single-kernel exclusive scan (decoupled lookback) ----------------
__global__ __launch_bounds__(512) void k_scan() {
    int b = blockIdx.x, t = threadIdx.x;
    int gid = b * 512 + t;
    int v = (gid < NN) ? g_cnt[gid] : 0;

    __shared__ int s[512];
    s[t] = v;
    for (int off = 1; off < 512; off <<= 1) {
        __syncthreads();
        int add = (t >= off) ? s[t - off] : 0;
        __syncthreads();
        s[t] += add;
    }
    __syncthreads();
    int incl  = s[t];
    int total = s[511];

    __shared__ int sExcl;
    if (t == 0) {
        if (b == 0) {
            atomicExch(&g_state[0], (2u << 30) | (unsigned)total);
            sExcl = 0;
        } else {
            atomicExch(&g_state[b], (1u << 30) | (unsigned)total);
            int excl = 0, j = b - 1;
            while (true) {
                unsigned st;
                do { st = atomicAdd(&g_state[j], 0u); } while ((st >> 30) == 0u);
                excl += (int)(st & 0x3FFFFFFFu);
                if ((st >> 30) == 2u) break;
                --j;
            }
            atomicExch(&g_state[b], (2u << 30) | (unsigned)(excl + total));
            sExcl = excl;
        }
    }
    __syncthreads();
    int rs = sExcl + incl - v;   // exclusive prefix
    if (gid < NN) { g_row_start[gid] = rs; g_cursor[gid] = rs; }
    if (gid == 0) g_row_start[NN] = EE;
}

// ---------------- CSR fill + scratch reset for next call ----------------
__global__ void k_fill(const int* __restrict__ ei) {
    int e = blockIdx.x * blockDim.x + threadIdx.x;
    if (e < EE) {
        int d = ei[EE + e];
        int pos = atomicAdd(&g_cursor[d], 1);
        g_csr[pos] = ei[e];
    }
    // g_cnt/g_state are dead after k_scan: reset them here for the next call
    if (e < NN) g_cnt[e] = 0;
    if (e < 256) g_state[e] = 0;
}

// ---------------- layer-1 mean aggregation ----------------
// Warp per node, half-warp per edge: lane=(sub,chunk), uint4 (8-half) loads.
// 2 edges per warp-iteration (x2 unroll = 4), fp32 accumulate, fp16 row out.
__global__ void k_agg1() {
    int warp = threadIdx.x >> 5, lane = threadIdx.x & 31;
    int node = blockIdx.x * 8 + warp;
    if (node >= NN) return;
    int beg = g_row_start[node], end = g_row_start[node + 1];
    int sub = lane >> 4, chunk = lane & 15;
    const uint4* xv = (const uint4*)g_x16;   // 16 uint4 per row
    float acc[8];
    #pragma unroll
    for (int i = 0; i < 8; ++i) acc[i] = 0.f;

    int e = beg;
    for (; e + 3 < end; e += 4) {
        int sA = g_csr[e + sub];
        int sB = g_csr[e + 2 + sub];
        uint4 dA = xv[(size_t)sA * 16 + chunk];
        uint4 dB = xv[(size_t)sB * 16 + chunk];
        float2 a0 = __half22float2(*(__half2*)&dA.x);
        float2 a1 = __half22float2(*(__half2*)&dA.y);
        float2 a2 = __half22float2(*(__half2*)&dA.z);
        float2 a3 = __half22float2(*(__half2*)&dA.w);
        float2 b0 = __half22float2(*(__half2*)&dB.x);
        float2 b1 = __half22float2(*(__half2*)&dB.y);
        float2 b2 = __half22float2(*(__half2*)&dB.z);
        float2 b3 = __half22float2(*(__half2*)&dB.w);
        acc[0] += a0.x + b0.x; acc[1] += a0.y + b0.y;
        acc[2] += a1.x + b1.x; acc[3] += a1.y + b1.y;
        acc[4] += a2.x + b2.x; acc[5] += a2.y + b2.y;
        acc[6] += a3.x + b3.x; acc[7] += a3.y + b3.y;
    }
    if (e + 1 < end) {       // one more pair
        int sA = g_csr[e + sub];
        uint4 dA = xv[(size_t)sA * 16 + chunk];
        float2 a0 = __half22float2(*(__half2*)&dA.x);
        float2 a1 = __half22float2(*(__half2*)&dA.y);
        float2 a2 = __half22float2(*(__half2*)&dA.z);
        float2 a3 = __half22float2(*(__half2*)&dA.w);
        acc[0] += a0.x; acc[1] += a0.y; acc[2] += a1.x; acc[3] += a1.y;
        acc[4] += a2.x; acc[5] += a2.y; acc[6] += a3.x; acc[7] += a3.y;
        e += 2;
    }
    if (e < end && sub == 0) {   // single-edge tail (sub 0 only)
        int sA = g_csr[e];
        uint4 dA = xv[(size_t)sA * 16 + chunk];
        float2 a0 = __half22float2(*(__half2*)&dA.x);
        float2 a1 = __half22float2(*(__half2*)&dA.y);
        float2 a2 = __half22float2(*(__half2*)&dA.z);
        float2 a3 = __half22float2(*(__half2*)&dA.w);
        acc[0] += a0.x; acc[1] += a0.y; acc[2] += a1.x; acc[3] += a1.y;
        acc[4] += a2.x; acc[5] += a2.y; acc[6] += a3.x; acc[7] += a3.y;
    }
    // combine the two half-warps
    #pragma unroll
    for (int i = 0; i < 8; ++i) acc[i] += __shfl_down_sync(FULL, acc[i], 16);
    if (sub == 0) {
        float inv = (end > beg) ? 1.0f / (float)(end - beg) : 0.f;
        uint4 o;
        *(__half2*)&o.x = __floats2half2_rn(acc[0] * inv, acc[1] * inv);
        *(__half2*)&o.y = __floats2half2_rn(acc[2] * inv, acc[3] * inv);
        *(__half2*)&o.z = __floats2half2_rn(acc[4] * inv, acc[5] * inv);
        *(__half2*)&o.w = __floats2half2_rn(acc[6] * inv, acc[7] * inv);
        ((uint4*)g_aggx16)[(size_t)node * 16 + chunk] = o;
    }
}

// ---------------- helpers ----------------
__device__ __forceinline__ uint32_t smem_u32(const void* p) {
    uint32_t a;
    asm("{ .reg .u64 t; cvta.to.shared.u64 t, %1; cvt.u32.u64 %0, t; }" : "=r"(a) : "l"(p));
    return a;
}
__device__ __forceinline__ void ldm_x4(uint32_t* r, uint32_t addr) {
    asm volatile("ldmatrix.sync.aligned.m8n8.x4.shared.b16 {%0,%1,%2,%3}, [%4];"
                 : "=r"(r[0]), "=r"(r[1]), "=r"(r[2]), "=r"(r[3]) : "r"(addr));
}
__device__ __forceinline__ void ldm_x2(uint32_t* r, uint32_t addr) {
    asm volatile("ldmatrix.sync.aligned.m8n8.x2.shared.b16 {%0,%1}, [%2];"
                 : "=r"(r[0]), "=r"(r[1]) : "r"(addr));
}
__device__ __forceinline__ void mma_f16(float* c, const uint32_t* a, const uint32_t* b) {
    asm volatile(
        "mma.sync.aligned.m16n8k16.row.col.f32.f16.f16.f32 "
        "{%0,%1,%2,%3}, {%4,%5,%6,%7}, {%8,%9}, {%0,%1,%2,%3};"
        : "+f"(c[0]), "+f"(c[1]), "+f"(c[2]), "+f"(c[3])
        : "r"(a[0]), "r"(a[1]), "r"(a[2]), "r"(a[3]), "r"(b[0]), "r"(b[1]));
}
__device__ __forceinline__ void cp16(uint32_t smem_addr, const void* gptr) {
    asm volatile("cp.async.cg.shared.global [%0], [%1], 16;"
                 :: "r"(smem_addr), "l"(gptr) : "memory");
}
__device__ __forceinline__ void cp16z(uint32_t smem_addr, const void* gptr, uint32_t sz) {
    asm volatile("cp.async.cg.shared.global [%0], [%1], 16, %2;"
                 :: "r"(smem_addr), "l"(gptr), "r"(sz) : "memory");
}
__device__ __forceinline__ void cp_commit() {
    asm volatile("cp.async.commit_group;" ::: "memory");
}
__device__ __forceinline__ void cp_wait0() {
    asm volatile("cp.async.wait_group 0;" ::: "memory");
}

// smem layout (bytes) — double-buffered fp16 A/B tiles
#define SA    0            // 2 x [64][64] f16 swizzled    (2 x 8 KB)
#define SB    16384        // 2 x [256][64] f16 swizzled   (2 x 32 KB)
#define SM_W2 81920        // [8][256] f32 (8 KB)
#define SM_B1 90112        // [256] f32 (1 KB)
#define SM_TOT 91136
// h buffer [64][264] f32 = 67584 B reuses [0, 67584) after mainloop

// ---------------- mma.sync fp16 GEMM + fused layer-2 projection ----------------
// Per CTA: rows rowBase..rowBase+63, all 256 output cols. 8 warps, warp tile 64x32.
// D = A16 * W16 (fp32 accum). All tiles via cp.async double buffering. 2 CTAs/SM.
__global__ __launch_bounds__(256, 2) void k_mma(
    const float* __restrict__ b1,
    const float* __restrict__ w2l, const float* __restrict__ w2r)
{
    extern __shared__ char smem[];
    uint32_t sb = smem_u32(smem);
    int tid = threadIdx.x, wid = tid >> 5, lane = tid & 31;
    int rowBase = blockIdx.x * 64;

    int arow = tid >> 2, apart = tid & 3;      // A: 4 threads/row, 2 x 16B chunks each
    int grow = rowBase + arow;
    uint32_t asz = (grow < NN) ? 16u : 0u;     // zero-fill OOB rows

    auto issueA = [&](int kc, int buf) {
        const __half* src = (kc < 2) ? (g_aggx16 + (size_t)grow * 128 + kc * 64)
                                     : (g_x16    + (size_t)grow * 128 + (kc - 2) * 64);
        uint32_t dst = sb + SA + buf * 8192 + arow * 128;
        #pragma unroll
        for (int q = 0; q < 2; ++q) {
            int c = apart * 2 + q;
            cp16z(dst + ((c ^ (arow & 7)) << 4), src + c * 8, asz);
        }
    };
    auto issueB = [&](int kc, int buf) {
        uint32_t dst = sb + SB + buf * 32768 + tid * 128;
        const __half* ph = g_w1h + tid * 256 + kc * 64;
        #pragma unroll
        for (int q = 0; q < 8; ++q)
            cp16(dst + ((q ^ (tid & 7)) << 4), ph + q * 8);
    };

    // ---- prologue: kick off chunk 0, stage w2/b1 ----
    issueA(0, 0);
    issueB(0, 0);
    cp_commit();
    {
        int o = tid >> 5, k = (tid & 31) * 8;
        const float* wp = (o < 4) ? (w2l + o * 256 + k) : (w2r + (o - 4) * 256 + k);
        *(float4*)(smem + SM_W2 + (size_t)(o * 256 + k) * 4)     = ((const float4*)wp)[0];
        *(float4*)(smem + SM_W2 + (size_t)(o * 256 + k + 4) * 4) = ((const float4*)wp)[1];
        if (tid < 64) *(float4*)(smem + SM_B1 + tid * 16) = ((const float4*)b1)[tid];
    }

    float C[4][4][4];
    #pragma unroll
    for (int mt = 0; mt < 4; ++mt)
        #pragma unroll
        for (int nt = 0; nt < 4; ++nt)
            #pragma unroll
            for (int q = 0; q < 4; ++q) C[mt][nt][q] = 0.f;

    #pragma unroll
    for (int kc = 0; kc < 4; ++kc) {
        int buf = kc & 1;
        cp_wait0();
        __syncthreads();   // tiles[kc] visible to all; prior-buf reads done

        if (kc < 3) {      // overlap next chunk's loads with this chunk's MMAs
            issueA(kc + 1, buf ^ 1);
            issueB(kc + 1, buf ^ 1);
            cp_commit();
        }

        uint32_t baseA = sb + SA + buf * 8192;
        uint32_t baseB = sb + SB + buf * 32768;
        #pragma unroll
        for (int ks = 0; ks < 4; ++ks) {
            uint32_t Ah[4][4], Bh[4][2];
            int ar = lane & 15, ac = ks * 2 + (lane >> 4);
            #pragma unroll
            for (int mt = 0; mt < 4; ++mt) {
                int r = mt * 16 + ar;
                ldm_x4(Ah[mt], baseA + r * 128 + ((ac ^ (r & 7)) << 4));
            }
            int br = lane & 7, bc = ks * 2 + ((lane >> 3) & 1);
            #pragma unroll
            for (int nt = 0; nt < 4; ++nt) {
                int r = wid * 32 + nt * 8 + br;
                ldm_x2(Bh[nt], baseB + r * 128 + ((bc ^ (r & 7)) << 4));
            }
            #pragma unroll
            for (int mt = 0; mt < 4; ++mt)
                #pragma unroll
                for (int nt = 0; nt < 4; ++nt)
                    mma_f16(C[mt][nt], Ah[mt], Bh[nt]);
        }
    }
    __syncthreads();   // all frag reads done; tile smem reusable as h buffer

    // ---- epilogue: bias + relu -> smem h[64][264] ----
    float* hs  = (float*)smem;
    const float* b1s = (const float*)(smem + SM_B1);
    const float* w2s = (const float*)(smem + SM_W2);
    {
        int rq = lane >> 2, cq = (lane & 3) * 2;
        #pragma unroll
        for (int mt = 0; mt < 4; ++mt)
            #pragma unroll
            for (int nt = 0; nt < 4; ++nt) {
                int col = wid * 32 + nt * 8 + cq;
                float bx = b1s[col], by = b1s[col + 1];
                int r0 = mt * 16 + rq, r1 = r0 + 8;
                float v00 = C[mt][nt][0] + bx, v01 = C[mt][nt][1] + by;
                float v10 = C[mt][nt][2] + bx, v11 = C[mt][nt][3] + by;
                *(float2*)&hs[r0 * 264 + col] =
                    make_float2(v00 > 0.f ? v00 : 0.f, v01 > 0.f ? v01 : 0.f);
                *(float2*)&hs[r1 * 264 + col] =
                    make_float2(v10 > 0.f ? v10 : 0.f, v11 > 0.f ? v11 : 0.f);
            }
    }
    __syncthreads();

    // ---- layer-2 projection: warp per 8 rows ----
    #pragma unroll
    for (int rr = 0; rr < 8; ++rr) {
        int row = wid * 8 + rr;
        const float* hr = &hs[row * 264];
        float4 p0 = *(const float4*)&hr[lane * 8];
        float4 p1 = *(const float4*)&hr[lane * 8 + 4];
        float val = 0.f;
        #pragma unroll
        for (int o = 0; o < 8; ++o) {
            const float* wr = &w2s[o * 256 + lane * 8];
            float s = p0.x * wr[0] + p0.y * wr[1] + p0.z * wr[2] + p0.w * wr[3]
                    + p1.x * wr[4] + p1.y * wr[5] + p1.z * wr[6] + p1.w * wr[7];
            #pragma unroll
            for (int off = 16; off; off >>= 1) s += __shfl_xor_sync(FULL, s, off);
            if (lane == o) val = s;
        }
        int gr = rowBase + row;
        if (gr < NN) {
            if (lane < 4)      g_u[gr * 4 + lane]       = val;
            else if (lane < 8) g_v[gr * 4 + (lane - 4)] = val;
        }
    }
}

// ---------------- layer-2 aggregation + bias + residual + log_softmax ----------------
__global__ void k_final(const float* __restrict__ b2, float* __restrict__ out) {
    int warp = threadIdx.x >> 5, lane = threadIdx.x & 31;
    int node = blockIdx.x * 8 + warp;
    if (node >= NN) return;
    int beg = g_row_start[node], end = g_row_start[node + 1];
    int ei8 = lane >> 2, c = lane & 3;
    float acc = 0.f;
    for (int base = beg; base < end; base += 8) {
        int e = base + ei8;
        if (e < end) {
            int s = g_csr[e];
            acc += g_u[s * 4 + c];
        }
    }
    acc += __shfl_down_sync(FULL, acc, 16);
    acc += __shfl_down_sync(FULL, acc, 8);
    acc += __shfl_down_sync(FULL, acc, 4);
    float inv = (end > beg) ? 1.0f / (float)(end - beg) : 0.f;
    float val = acc * inv + b2[c] + g_v[node * 4 + c];
    float m = val;
    m = fmaxf(m, __shfl_xor_sync(FULL, m, 1));
    m = fmaxf(m, __shfl_xor_sync(FULL, m, 2));
    float ex = expf(val - m);
    float ssum = ex;
    ssum += __shfl_xor_sync(FULL, ssum, 1);
    ssum += __shfl_xor_sync(FULL, ssum, 2);
    if (lane < 4) out[node * 4 + c] = val - m - logf(ssum);
}

// ---------------- eager module load + smem opt-in (static init, outside capture) ----------------
namespace {
struct HXModuleLoad {
    HXModuleLoad() {
        cudaFuncAttributes a;
        (void)cudaFuncGetAttributes(&a, (const void*)k_prep);
        (void)cudaFuncSetAttribute((const void*)k_mma,
                                   cudaFuncAttributeMaxDynamicSharedMemorySize, SM_TOT);
    }
};
HXModuleLoad hx_module_load_;
}

// ---------------- launch ----------------
extern "C" void kernel_launch(void* const* d_in, const int* in_sizes, int n_in,
                              void* d_out, int out_size) {
    const float* x   = (const float*)d_in[0];
    const int*   ei  = (const int*)d_in[1];   // int32 edge_index: [0..E)=src, [E..2E)=dst
    const float* w1l = (const float*)d_in[2];
    const float* w1r = (const float*)d_in[3];
    const float* b1  = (const float*)d_in[4];
    const float* w2l = (const float*)d_in[5];
    const float* w2r = (const float*)d_in[6];
    const float* b2  = (const float*)d_in[7];
    float* out = (float*)d_out;

    k_prep<<<512, 256>>>(w1l, w1r, x, ei);            // 1: W/x -> fp16 + histogram
    k_scan<<<NB_SCAN, 512>>>();                       // 2: single-pass lookback scan
    k_fill<<<(EE + 255) / 256, 256>>>(ei);            // 3: CSR fill + reset cnt/state
    k_agg1<<<(NN + 7) / 8, 256>>>();                  // 4: fp16 gather-mean (uint4, 2 edges/iter)
    k_mma<<<(NN + 63) / 64, 256, SM_TOT>>>(b1, w2l, w2r);  // 5
    k_final<<<(NN + 7) / 8, 256>>>(b2, out);          // 6
}

// round 15
// speedup vs baseline: 1.9037x; 1.0577x over previous
#include <cuda_runtime.h>
#include <cuda_fp16.h>
#include <cstdint>

#define NN 100000
#define EE 1600000
#define FULL 0xffffffffu
#define NB_SCAN 196

// ---------------- scratch (static device globals; no allocation) ----------------
// NOTE: g_cnt/g_state are zero at module load and re-zeroed by k_fill each call
// (after k_scan consumes them), so k_prep's histogram always starts from zero.
__device__ __align__(16) int   g_cnt[NN];
__device__ __align__(16) int   g_row_start[NN + 1];
__device__ __align__(16) int   g_cursor[NN];
__device__ __align__(16) int   g_csr[EE];
__device__ __align__(16) unsigned int g_state[256];   // lookback: flag(2b)|value(30b)
__device__ __align__(16) __half g_x16[12800000];      // x in fp16 [N][128]
__device__ __align__(16) __half g_aggx16[12800000];   // mean-agg in fp16 [N][128]
__device__ __align__(16) float g_u[NN * 4];
__device__ __align__(16) float g_v[NN * 4];
__device__ __align__(16) __half g_w1h[65536];         // [256 out][256 k] fp16

// ---------------- prep: W->fp16, x->fp16, degree histogram ----------------
__global__ void k_prep(const float* __restrict__ w1l, const float* __restrict__ w1r,
                       const float* __restrict__ x, const int* __restrict__ ei) {
    int idx = blockIdx.x * 256 + threadIdx.x;   // 131072 threads
    // weights (first 65536 threads)
    if (idx < 65536) {
        int out = idx >> 8, k = idx & 255;
        float v = (k < 128) ? w1l[out * 128 + k] : w1r[out * 128 + (k - 128)];
        g_w1h[idx] = __float2half_rn(v);
    }
    // x -> fp16 (1.6M uint4 = 12.8M halves)
    const float4* xf = (const float4*)x;
    for (int i = idx; i < 1600000; i += 131072) {
        float4 a = xf[2 * i], b = xf[2 * i + 1];
        union { __half2 h2[4]; uint4 u; } P;
        P.h2[0] = __floats2half2_rn(a.x, a.y);
        P.h2[1] = __floats2half2_rn(a.z, a.w);
        P.h2[2] = __floats2half2_rn(b.x, b.y);
        P.h2[3] = __floats2half2_rn(b.z, b.w);
        ((uint4*)g_x16)[i] = P.u;
    }
    // in-degree histogram (g_cnt pre-zeroed by previous call's k_fill / module load)
    for (int e = idx; e < EE; e += 131072)
        atomicAdd(&g_cnt[ei[EE + e]], 1);
}

// ---------------- single-kernel exclusive scan (decoupled lookback) ----------------
__global__ __launch_bounds__(512) void k_scan() {
    int b = blockIdx.x, t = threadIdx.x;
    int gid = b * 512 + t;
    int v = (gid < NN) ? g_cnt[gid] : 0;

    __shared__ int s[512];
    s[t] = v;
    for (int off = 1; off < 512; off <<= 1) {
        __syncthreads();
        int add = (t >= off) ? s[t - off] : 0;
        __syncthreads();
        s[t] += add;
    }
    __syncthreads();
    int incl  = s[t];
    int total = s[511];

    __shared__ int sExcl;
    if (t == 0) {
        if (b == 0) {
            atomicExch(&g_state[0], (2u << 30) | (unsigned)total);
            sExcl = 0;
        } else {
            atomicExch(&g_state[b], (1u << 30) | (unsigned)total);
            int excl = 0, j = b - 1;
            while (true) {
                unsigned st;
                do { st = atomicAdd(&g_state[j], 0u); } while ((st >> 30) == 0u);
                excl += (int)(st & 0x3FFFFFFFu);
                if ((st >> 30) == 2u) break;
                --j;
            }
            atomicExch(&g_state[b], (2u << 30) | (unsigned)(excl + total));
            sExcl = excl;
        }
    }
    __syncthreads();
    int rs = sExcl + incl - v;   // exclusive prefix
    if (gid < NN) { g_row_start[gid] = rs; g_cursor[gid] = rs; }
    if (gid == 0) g_row_start[NN] = EE;
}

// ---------------- CSR fill + scratch reset for next call ----------------
__global__ void k_fill(const int* __restrict__ ei) {
    int e = blockIdx.x * blockDim.x + threadIdx.x;
    if (e < EE) {
        int d = ei[EE + e];
        int pos = atomicAdd(&g_cursor[d], 1);
        g_csr[pos] = ei[e];
    }
    // g_cnt/g_state are dead after k_scan: reset them here for the next call
    if (e < NN) g_cnt[e] = 0;
    if (e < 256) g_state[e] = 0;
}

// ---------------- layer-1 mean aggregation ----------------
// Warp per node, half-warp per edge: lane=(sub,chunk), uint4 (8-half) loads.
// HADD2 pair-combine (1 extra fp16 rounding), fp32 accumulate, fp16 row out.
__global__ void k_agg1() {
    int warp = threadIdx.x >> 5, lane = threadIdx.x & 31;
    int node = blockIdx.x * 8 + warp;
    if (node >= NN) return;
    int beg = g_row_start[node], end = g_row_start[node + 1];
    int sub = lane >> 4, chunk = lane & 15;
    const uint4* xv = (const uint4*)g_x16;   // 16 uint4 per row
    float acc[8];
    #pragma unroll
    for (int i = 0; i < 8; ++i) acc[i] = 0.f;

    int e = beg;
    for (; e + 3 < end; e += 4) {
        int sA = g_csr[e + sub];
        int sB = g_csr[e + 2 + sub];
        uint4 dA = xv[(size_t)sA * 16 + chunk];
        uint4 dB = xv[(size_t)sB * 16 + chunk];
        __half2 p0 = __hadd2(*(__half2*)&dA.x, *(__half2*)&dB.x);
        __half2 p1 = __hadd2(*(__half2*)&dA.y, *(__half2*)&dB.y);
        __half2 p2 = __hadd2(*(__half2*)&dA.z, *(__half2*)&dB.z);
        __half2 p3 = __hadd2(*(__half2*)&dA.w, *(__half2*)&dB.w);
        float2 f0 = __half22float2(p0);
        float2 f1 = __half22float2(p1);
        float2 f2 = __half22float2(p2);
        float2 f3 = __half22float2(p3);
        acc[0] += f0.x; acc[1] += f0.y; acc[2] += f1.x; acc[3] += f1.y;
        acc[4] += f2.x; acc[5] += f2.y; acc[6] += f3.x; acc[7] += f3.y;
    }
    if (e + 1 < end) {       // one more pair
        int sA = g_csr[e + sub];
        uint4 dA = xv[(size_t)sA * 16 + chunk];
        float2 a0 = __half22float2(*(__half2*)&dA.x);
        float2 a1 = __half22float2(*(__half2*)&dA.y);
        float2 a2 = __half22float2(*(__half2*)&dA.z);
        float2 a3 = __half22float2(*(__half2*)&dA.w);
        acc[0] += a0.x; acc[1] += a0.y; acc[2] += a1.x; acc[3] += a1.y;
        acc[4] += a2.x; acc[5] += a2.y; acc[6] += a3.x; acc[7] += a3.y;
        e += 2;
    }
    if (e < end && sub == 0) {   // single-edge tail (sub 0 only)
        int sA = g_csr[e];
        uint4 dA = xv[(size_t)sA * 16 + chunk];
        float2 a0 = __half22float2(*(__half2*)&dA.x);
        float2 a1 = __half22float2(*(__half2*)&dA.y);
        float2 a2 = __half22float2(*(__half2*)&dA.z);
        float2 a3 = __half22float2(*(__half2*)&dA.w);
        acc[0] += a0.x; acc[1] += a0.y; acc[2] += a1.x; acc[3] += a1.y;
        acc[4] += a2.x; acc[5] += a2.y; acc[6] += a3.x; acc[7] += a3.y;
    }
    // combine the two half-warps
    #pragma unroll
    for (int i = 0; i < 8; ++i) acc[i] += __shfl_down_sync(FULL, acc[i], 16);
    if (sub == 0) {
        float inv = (end > beg) ? 1.0f / (float)(end - beg) : 0.f;
        uint4 o;
        *(__half2*)&o.x = __floats2half2_rn(acc[0] * inv, acc[1] * inv);
        *(__half2*)&o.y = __floats2half2_rn(acc[2] * inv, acc[3] * inv);
        *(__half2*)&o.z = __floats2half2_rn(acc[4] * inv, acc[5] * inv);
        *(__half2*)&o.w = __floats2half2_rn(acc[6] * inv, acc[7] * inv);
        ((uint4*)g_aggx16)[(size_t)node * 16 + chunk] = o;
    }
}

// ---------------- helpers ----------------
__device__ __forceinline__ uint32_t smem_u32(const void* p) {
    uint32_t a;
    asm("{ .reg .u64 t; cvta.to.shared.u64 t, %1; cvt.u32.u64 %0, t; }" : "=r"(a) : "l"(p));
    return a;
}
__device__ __forceinline__ void ldm_x4(uint32_t* r, uint32_t addr) {
    asm volatile("ldmatrix.sync.aligned.m8n8.x4.shared.b16 {%0,%1,%2,%3}, [%4];"
                 : "=r"(r[0]), "=r"(r[1]), "=r"(r[2]), "=r"(r[3]) : "r"(addr));
}
__device__ __forceinline__ void ldm_x2(uint32_t* r, uint32_t addr) {
    asm volatile("ldmatrix.sync.aligned.m8n8.x2.shared.b16 {%0,%1}, [%2];"
                 : "=r"(r[0]), "=r"(r[1]) : "r"(addr));
}
__device__ __forceinline__ void mma_f16(float* c, const uint32_t* a, const uint32_t* b) {
    asm volatile(
        "mma.sync.aligned.m16n8k16.row.col.f32.f16.f16.f32 "
        "{%0,%1,%2,%3}, {%4,%5,%6,%7}, {%8,%9}, {%0,%1,%2,%3};"
        : "+f"(c[0]), "+f"(c[1]), "+f"(c[2]), "+f"(c[3])
        : "r"(a[0]), "r"(a[1]), "r"(a[2]), "r"(a[3]), "r"(b[0]), "r"(b[1]));
}
__device__ __forceinline__ void cp16(uint32_t smem_addr, const void* gptr) {
    asm volatile("cp.async.cg.shared.global [%0], [%1], 16;"
                 :: "r"(smem_addr), "l"(gptr) : "memory");
}
__device__ __forceinline__ void cp16z(uint32_t smem_addr, const void* gptr, uint32_t sz) {
    asm volatile("cp.async.cg.shared.global [%0], [%1], 16, %2;"
                 :: "r"(smem_addr), "l"(gptr), "r"(sz) : "memory");
}
__device__ __forceinline__ void cp_commit() {
    asm volatile("cp.async.commit_group;" ::: "memory");
}
__device__ __forceinline__ void cp_wait0() {
    asm volatile("cp.async.wait_group 0;" ::: "memory");
}

// smem layout (bytes) — BM=128, double-buffered fp16 A/B tiles
#define SA    0            // 2 x [128][64] f16 swizzled   (2 x 16 KB)
#define SB    32768        // 2 x [256][64] f16 swizzled   (2 x 32 KB)
#define SM_W2 135168       // [8][256] f32 (8 KB) — placed after h-buffer region
#define SM_B1 143360       // [256] f32 (1 KB)
#define SM_TOT 144384
// h buffer [128][264] f32 = 135168 B reuses [0, 135168) after mainloop

// ---------------- mma.sync fp16 GEMM + fused layer-2 projection ----------------
// Per CTA: rows rowBase..rowBase+127, all 256 output cols. 16 warps (2x8),
// warp tile 64x32. D = A16 * W16 (fp32 accum). cp.async double buffering.
__global__ __launch_bounds__(512, 1) void k_mma(
    const float* __restrict__ b1,
    const float* __restrict__ w2l, const float* __restrict__ w2r)
{
    extern __shared__ char smem[];
    uint32_t sb = smem_u32(smem);
    int tid = threadIdx.x, wid = tid >> 5, lane = tid & 31;
    int rowBase = blockIdx.x * 128;
    int wr = wid & 1, wc = wid >> 1;           // warp grid: 2 rows x 8 cols

    int arow = tid >> 2, apart = tid & 3;      // A: 4 threads/row (128 rows), 2 x 16B each
    int grow = rowBase + arow;
    uint32_t asz = (grow < NN) ? 16u : 0u;     // zero-fill OOB rows

    int brow = tid >> 1, bhalf = tid & 1;      // B: 2 threads/row (256 rows), 4 x 16B each

    auto issueA = [&](int kc, int buf) {
        const __half* src = (kc < 2) ? (g_aggx16 + (size_t)grow * 128 + kc * 64)
                                     : (g_x16    + (size_t)grow * 128 + (kc - 2) * 64);
        uint32_t dst = sb + SA + buf * 16384 + arow * 128;
        #pragma unroll
        for (int q = 0; q < 2; ++q) {
            int c = apart * 2 + q;
            cp16z(dst + ((c ^ (arow & 7)) << 4), src + c * 8, asz);
        }
    };
    auto issueB = [&](int kc, int buf) {
        uint32_t dst = sb + SB + buf * 32768 + brow * 128;
        const __half* ph = g_w1h + brow * 256 + kc * 64 + bhalf * 32;
        #pragma unroll
        for (int q = 0; q < 4; ++q) {
            int c = bhalf * 4 + q;
            cp16(dst + ((c ^ (brow & 7)) << 4), ph + q * 8);
        }
    };

    // ---- prologue: kick off chunk 0, stage w2/b1 ----
    issueA(0, 0);
    issueB(0, 0);
    cp_commit();
    if (tid < 256) {
        int o = tid >> 5, k = (tid & 31) * 8;
        const float* wp = (o < 4) ? (w2l + o * 256 + k) : (w2r + (o - 4) * 256 + k);
        *(float4*)(smem + SM_W2 + (size_t)(o * 256 + k) * 4)     = ((const float4*)wp)[0];
        *(float4*)(smem + SM_W2 + (size_t)(o * 256 + k + 4) * 4) = ((const float4*)wp)[1];
        if (tid < 64) *(float4*)(smem + SM_B1 + tid * 16) = ((const float4*)b1)[tid];
    }

    float C[4][4][4];
    #pragma unroll
    for (int mt = 0; mt < 4; ++mt)
        #pragma unroll
        for (int nt = 0; nt < 4; ++nt)
            #pragma unroll
            for (int q = 0; q < 4; ++q) C[mt][nt][q] = 0.f;

    #pragma unroll
    for (int kc = 0; kc < 4; ++kc) {
        int buf = kc & 1;
        cp_wait0();
        __syncthreads();   // tiles[kc] visible to all; prior-buf reads done

        if (kc < 3) {      // overlap next chunk's loads with this chunk's MMAs
            issueA(kc + 1, buf ^ 1);
            issueB(kc + 1, buf ^ 1);
            cp_commit();
        }

        uint32_t baseA = sb + SA + buf * 16384;
        uint32_t baseB = sb + SB + buf * 32768;
        #pragma unroll
        for (int ks = 0; ks < 4; ++ks) {
            uint32_t Ah[4][4], Bh[4][2];
            int ar = lane & 15, ac = ks * 2 + (lane >> 4);
            #pragma unroll
            for (int mt = 0; mt < 4; ++mt) {
                int r = wr * 64 + mt * 16 + ar;
                ldm_x4(Ah[mt], baseA + r * 128 + ((ac ^ (r & 7)) << 4));
            }
            int br = lane & 7, bc = ks * 2 + ((lane >> 3) & 1);
            #pragma unroll
            for (int nt = 0; nt < 4; ++nt) {
                int r = wc * 32 + nt * 8 + br;
                ldm_x2(Bh[nt], baseB + r * 128 + ((bc ^ (r & 7)) << 4));
            }
            #pragma unroll
            for (int mt = 0; mt < 4; ++mt)
                #pragma unroll
                for (int nt = 0; nt < 4; ++nt)
                    mma_f16(C[mt][nt], Ah[mt], Bh[nt]);
        }
    }
    __syncthreads();   // all frag reads done; tile smem reusable as h buffer

    // ---- epilogue: bias + relu -> smem h[128][264] ----
    float* hs  = (float*)smem;
    const float* b1s = (const float*)(smem + SM_B1);
    const float* w2s = (const float*)(smem + SM_W2);
    {
        int rq = lane >> 2, cq = (lane & 3) * 2;
        #pragma unroll
        for (int mt = 0; mt < 4; ++mt)
            #pragma unroll
            for (int nt = 0; nt < 4; ++nt) {
                int col = wc * 32 + nt * 8 + cq;
                float bx = b1s[col], by = b1s[col + 1];
                int r0 = wr * 64 + mt * 16 + rq, r1 = r0 + 8;
                float v00 = C[mt][nt][0] + bx, v01 = C[mt][nt][1] + by;
                float v10 = C[mt][nt][2] + bx, v11 = C[mt][nt][3] + by;
                *(float2*)&hs[r0 * 264 + col] =
                    make_float2(v00 > 0.f ? v00 : 0.f, v01 > 0.f ? v01 : 0.f);
                *(float2*)&hs[r1 * 264 + col] =
                    make_float2(v10 > 0.f ? v10 : 0.f, v11 > 0.f ? v11 : 0.f);
            }
    }
    __syncthreads();

    // ---- layer-2 projection: warp per 8 rows (16 warps x 8 = 128 rows) ----
    #pragma unroll
    for (int rr = 0; rr < 8; ++rr) {
        int row = wid * 8 + rr;
        const float* hr = &hs[row * 264];
        float4 p0 = *(const float4*)&hr[lane * 8];
        float4 p1 = *(const float4*)&hr[lane * 8 + 4];
        float val = 0.f;
        #pragma unroll
        for (int o = 0; o < 8; ++o) {
            const float* wr2 = &w2s[o * 256 + lane * 8];
            float s = p0.x * wr2[0] + p0.y * wr2[1] + p0.z * wr2[2] + p0.w * wr2[3]
                    + p1.x * wr2[4] + p1.y * wr2[5] + p1.z * wr2[6] + p1.w * wr2[7];
            #pragma unroll
            for (int off = 16; off; off >>= 1) s += __shfl_xor_sync(FULL, s, off);
            if (lane == o) val = s;
        }
        int gr = rowBase + row;
        if (gr < NN) {
            if (lane < 4)      g_u[gr * 4 + lane]       = val;
            else if (lane < 8) g_v[gr * 4 + (lane - 4)] = val;
        }
    }
}

// ---------------- layer-2 aggregation + bias + residual + log_softmax ----------------
__global__ void k_final(const float* __restrict__ b2, float* __restrict__ out) {
    int warp = threadIdx.x >> 5, lane = threadIdx.x & 31;
    int node = blockIdx.x * 8 + warp;
    if (node >= NN) return;
    int beg = g_row_start[node], end = g_row_start[node + 1];
    int ei8 = lane >> 2, c = lane & 3;
    float acc = 0.f;
    for (int base = beg; base < end; base += 8) {
        int e = base + ei8;
        if (e < end) {
            int s = g_csr[e];
            acc += g_u[s * 4 + c];
        }
    }
    acc += __shfl_down_sync(FULL, acc, 16);
    acc += __shfl_down_sync(FULL, acc, 8);
    acc += __shfl_down_sync(FULL, acc, 4);
    float inv = (end > beg) ? 1.0f / (float)(end - beg) : 0.f;
    float val = acc * inv + b2[c] + g_v[node * 4 + c];
    float m = val;
    m = fmaxf(m, __shfl_xor_sync(FULL, m, 1));
    m = fmaxf(m, __shfl_xor_sync(FULL, m, 2));
    float ex = expf(val - m);
    float ssum = ex;
    ssum += __shfl_xor_sync(FULL, ssum, 1);
    ssum += __shfl_xor_sync(FULL, ssum, 2);
    if (lane < 4) out[node * 4 + c] = val - m - logf(ssum);
}

// ---------------- eager module load + smem opt-in (static init, outside capture) ----------------
namespace {
struct HXModuleLoad {
    HXModuleLoad() {
        cudaFuncAttributes a;
        (void)cudaFuncGetAttributes(&a, (const void*)k_prep);
        (void)cudaFuncSetAttribute((const void*)k_mma,
                                   cudaFuncAttributeMaxDynamicSharedMemorySize, SM_TOT);
    }
};
HXModuleLoad hx_module_load_;
}

// ---------------- launch ----------------
extern "C" void kernel_launch(void* const* d_in, const int* in_sizes, int n_in,
                              void* d_out, int out_size) {
    const float* x   = (const float*)d_in[0];
    const int*   ei  = (const int*)d_in[1];   // int32 edge_index: [0..E)=src, [E..2E)=dst
    const float* w1l = (const float*)d_in[2];
    const float* w1r = (const float*)d_in[3];
    const float* b1  = (const float*)d_in[4];
    const float* w2l = (const float*)d_in[5];
    const float* w2r = (const float*)d_in[6];
    const float* b2  = (const float*)d_in[7];
    float* out = (float*)d_out;

    k_prep<<<512, 256>>>(w1l, w1r, x, ei);            // 1: W/x -> fp16 + histogram
    k_scan<<<NB_SCAN, 512>>>();                       // 2: single-pass lookback scan
    k_fill<<<(EE + 255) / 256, 256>>>(ei);            // 3: CSR fill + reset cnt/state
    k_agg1<<<(NN + 7) / 8, 256>>>();                  // 4: fp16 gather-mean (HADD2+uint4)
    k_mma<<<(NN + 127) / 128, 512, SM_TOT>>>(b1, w2l, w2r);  // 5: BM=128
    k_final<<<(NN + 7) / 8, 256>>>(b2, out);          // 6
}